// round 14
// baseline (speedup 1.0000x reference)
#include <cuda_runtime.h>
#include <cuda_bf16.h>
#include <math.h>
#include <stdint.h>

#define BATCH 4
#define SEQ 1024
#define DMODEL 512
#define NHEAD 8
#define DHEAD 64
#define DINNER 1024
#define NLAYERS 2
#define NTOK (BATCH*SEQ)          // 4096
#define EPS 1e-3f
#define INV_TEMPER 0.044194173824159216f   // 1/sqrt(512)

typedef __nv_bfloat16 bf16;

// ------------------------- scratch (device globals; no runtime alloc) -----
__device__ float g_x  [NTOK*DMODEL];       // fp32 activations (residual path)
__device__ float g_att[NTOK*DMODEL];
__device__ float g_o  [NTOK*DMODEL];
__device__ bf16 g_xh[NTOK*DMODEL],  g_xl[NTOK*DMODEL];
__device__ bf16 g_hh[NTOK*DINNER],  g_hl[NTOK*DINNER];
__device__ bf16 g_wqkvh[NLAYERS*3*NHEAD*DHEAD*DMODEL];
__device__ bf16 g_wqkvl[NLAYERS*3*NHEAD*DHEAD*DMODEL];
__device__ bf16 g_w1h[NLAYERS*DINNER*DMODEL], g_w1l[NLAYERS*DINNER*DMODEL];
__device__ bf16 g_w2h[NLAYERS*DMODEL*DINNER], g_w2l[NLAYERS*DMODEL*DINNER];
__device__ bf16 g_qkv_h[3*NHEAD*NTOK*DHEAD];
__device__ bf16 g_qkv_l[3*NHEAD*NTOK*DHEAD];

// ------------------------- small helpers ----------------------------------
__device__ __forceinline__ uint32_t pack_bf16(bf16 a, bf16 b)
{
    __nv_bfloat162 t = __halves2bfloat162(a, b);
    return *(uint32_t*)&t;
}
__device__ __forceinline__ void split1(float v, bf16& h, bf16& l)
{
    h = __float2bfloat16(v);
    l = __float2bfloat16(v - __bfloat162float(h));
}
__device__ __forceinline__ float join1(bf16 h, bf16 l)
{
    return __bfloat162float(h) + __bfloat162float(l);
}

// ------------------------- x + pos_enc (fp32 + planes) --------------------
__global__ void add_pos_kernel(const float* __restrict__ x,
                               const float* __restrict__ pos,
                               float* __restrict__ y,
                               bf16* __restrict__ yh, bf16* __restrict__ yl)
{
    int idx = blockIdx.x * 512 + threadIdx.x;
    float v = x[idx] + pos[idx & (SEQ*DMODEL - 1)];
    y[idx] = v;
    bf16 h, l; split1(v, h, l);
    yh[idx] = h; yl[idx] = l;
}

// ------------------------- qkv weight transpose + split -------------------
__global__ void transpose3_kernel(const float* __restrict__ wq,
                                  const float* __restrict__ wk,
                                  const float* __restrict__ wv,
                                  bf16* __restrict__ oh, bf16* __restrict__ ol)
{
    __shared__ float tile[32][33];
    const int z = blockIdx.z;
    const int w = z / (NLAYERS*NHEAD);
    const int l = (z / NHEAD) % NLAYERS;
    const int h = z % NHEAD;
    const float* ip = (w == 0 ? wq : w == 1 ? wk : wv)
                      + (long)(l*NHEAD + h) * DMODEL * DHEAD;
    const long ob = (long)((l*3 + w)*NHEAD + h) * DHEAD * DMODEL;
    int c0 = blockIdx.x * 32, r0 = blockIdx.y * 32;
    for (int i = threadIdx.y; i < 32; i += 8)
        tile[i][threadIdx.x] = ip[(long)(r0 + i) * DHEAD + c0 + threadIdx.x];
    __syncthreads();
    for (int i = threadIdx.y; i < 32; i += 8) {
        float v = tile[threadIdx.x][i];
        bf16 hh, ll; split1(v, hh, ll);
        long o = ob + (long)(c0 + i) * DMODEL + r0 + threadIdx.x;
        oh[o] = hh; ol[o] = ll;
    }
}

// ------------------------- generic fp32 -> split planes -------------------
__global__ void split_kernel(const float* __restrict__ in,
                             bf16* __restrict__ oh, bf16* __restrict__ ol, int n)
{
    int idx = (blockIdx.x * 256 + threadIdx.x) * 4;
    if (idx >= n) return;
    float4 v = *(const float4*)(in + idx);
    bf16 h0,l0,h1,l1,h2,l2,h3,l3;
    split1(v.x,h0,l0); split1(v.y,h1,l1); split1(v.z,h2,l2); split1(v.w,h3,l3);
    *(uint2*)(oh + idx) = make_uint2(pack_bf16(h0,h1), pack_bf16(h2,h3));
    *(uint2*)(ol + idx) = make_uint2(pack_bf16(l0,l1), pack_bf16(l2,l3));
}

// ------------------------- mma / ldsm / cp.async helpers ------------------
__device__ __forceinline__ void ldsm4(uint32_t* r, uint32_t addr)
{
    asm volatile("ldmatrix.sync.aligned.m8n8.x4.shared.b16 {%0,%1,%2,%3}, [%4];"
        : "=r"(r[0]), "=r"(r[1]), "=r"(r[2]), "=r"(r[3]) : "r"(addr));
}
__device__ __forceinline__ void ldsm4t(uint32_t* r, uint32_t addr)
{
    asm volatile("ldmatrix.sync.aligned.m8n8.x4.trans.shared.b16 {%0,%1,%2,%3}, [%4];"
        : "=r"(r[0]), "=r"(r[1]), "=r"(r[2]), "=r"(r[3]) : "r"(addr));
}
__device__ __forceinline__ void mma_bf16(float* c, const uint32_t* a,
                                         uint32_t b0, uint32_t b1)
{
    asm volatile(
        "mma.sync.aligned.m16n8k16.row.col.f32.bf16.bf16.f32 "
        "{%0,%1,%2,%3}, {%4,%5,%6,%7}, {%8,%9}, {%0,%1,%2,%3};\n"
        : "+f"(c[0]), "+f"(c[1]), "+f"(c[2]), "+f"(c[3])
        : "r"(a[0]), "r"(a[1]), "r"(a[2]), "r"(a[3]), "r"(b0), "r"(b1));
}
__device__ __forceinline__ void packsplit(float x, float y, uint32_t& hi, uint32_t& lo)
{
    bf16 hx = __float2bfloat16(x), hy = __float2bfloat16(y);
    hi = pack_bf16(hx, hy);
    lo = pack_bf16(__float2bfloat16(x - __bfloat162float(hx)),
                   __float2bfloat16(y - __bfloat162float(hy)));
}
__device__ __forceinline__ void cpa16(uint32_t dst, const void* src)
{
    asm volatile("cp.async.cg.shared.global [%0], [%1], 16;\n" :: "r"(dst), "l"(src));
}
__device__ __forceinline__ void cpa_commit()
{
    asm volatile("cp.async.commit_group;\n");
}
template<int N> __device__ __forceinline__ void cpa_wait()
{
    asm volatile("cp.async.wait_group %0;\n" :: "n"(N));
}
// GEMM smem swizzle: 64B rows (32 bf16), 4x16B chunks
__device__ __forceinline__ int swoff(int row, int chunk)
{
    return row * 64 + ((chunk ^ ((row >> 1) & 3)) * 16);
}
// attention plane swizzle: 128B rows (64 bf16), 8x16B chunks
__device__ __forceinline__ uint32_t swz128(int row, int c16)
{
    return (uint32_t)(row * 128 + ((c16 ^ (row & 7)) * 16));
}

// ----------------- hybrid GEMM: HMMA blocks + SIMT-FMA blocks --------------
// C = A * B^T; A,B given as hi/lo bf16 planes (row-major, K contiguous).
// HMMA path: BM=128, BN=64, BK=32, 3-term split-bf16, 3-stage cp.async.
// SIMT path (blockIdx.x >= simt_x0 || blockIdx.z >= simt_z0): same 128x64
// tile computed on the FMA pipe in fp32 (A,B reconstructed as hi+lo).
// QSCALEZ: blocks with blockIdx.z < QSCALEZ scale output by 1/temper.
#define GEMM_SMEM 73728

template<int QSCALEZ, bool RELU, bool HASBIAS, bool SPLIT>
__global__ __launch_bounds__(256, 2)
void mma_gemm_bf(const bf16* __restrict__ Ah, const bf16* __restrict__ Al,
                 const bf16* __restrict__ Bh, const bf16* __restrict__ Bl,
                 float* __restrict__ C, const float* __restrict__ bias,
                 bf16* __restrict__ Chi, bf16* __restrict__ Clo,
                 int M, int N, int K, long strideB, long strideC,
                 int simt_x0, int simt_z0)
{
    extern __shared__ uint8_t sm[];
    Bh += (long)blockIdx.z * strideB;
    Bl += (long)blockIdx.z * strideB;
    if (SPLIT) { Chi += (long)blockIdx.z * strideC; Clo += (long)blockIdx.z * strideC; }
    else       { C   += (long)blockIdx.z * strideC; }
    const int bm = blockIdx.y * 128, bn = blockIdx.x * 64;
    const int tid = threadIdx.x;
    const bool qscale = (QSCALEZ > 0) && ((int)blockIdx.z < QSCALEZ);

    const bool is_simt = ((int)blockIdx.x >= simt_x0) || ((int)blockIdx.z >= simt_z0);

    if (is_simt) {
        // ---------------- SIMT fp32 path (FMA pipe) -----------------------
        // 128x64 tile, BK=16, 256 threads, 8x4 per thread.
        float* As = (float*)sm;                 // [16][129]
        float* Bs = As + 16 * 129;              // [16][65]

        const int arow = tid >> 1, ak = (tid & 1) * 8;
        const int brow = tid >> 2, bk = tid & 3;      // bk*4 k-offset
        const long aoff = (long)(bm + arow) * K;
        const long boff = (long)(bn + brow) * K;

        const int tr8 = (tid >> 4) * 8;
        const int tc4 = (tid & 15) * 4;
        float acc[8][4];
        #pragma unroll
        for (int i = 0; i < 8; ++i)
            #pragma unroll
            for (int j = 0; j < 4; ++j) acc[i][j] = 0.f;

        for (int k0 = 0; k0 < K; k0 += 16) {
            __syncthreads();
            {   // load A: 8 consecutive k per thread, reconstruct fp32
                uint4 hv = *(const uint4*)(Ah + aoff + k0 + ak);
                uint4 lv = *(const uint4*)(Al + aoff + k0 + ak);
                const uint32_t* hw = (const uint32_t*)&hv;
                const uint32_t* lw = (const uint32_t*)&lv;
                #pragma unroll
                for (int p = 0; p < 4; ++p) {
                    __nv_bfloat162 h2 = *(const __nv_bfloat162*)&hw[p];
                    __nv_bfloat162 l2 = *(const __nv_bfloat162*)&lw[p];
                    As[(ak + 2*p)     * 129 + arow] =
                        __bfloat162float(__low2bfloat16(h2)) +
                        __bfloat162float(__low2bfloat16(l2));
                    As[(ak + 2*p + 1) * 129 + arow] =
                        __bfloat162float(__high2bfloat16(h2)) +
                        __bfloat162float(__high2bfloat16(l2));
                }
            }
            {   // load B: 4 consecutive k per thread
                uint2 hv = *(const uint2*)(Bh + boff + k0 + bk*4);
                uint2 lv = *(const uint2*)(Bl + boff + k0 + bk*4);
                const uint32_t* hw = (const uint32_t*)&hv;
                const uint32_t* lw = (const uint32_t*)&lv;
                #pragma unroll
                for (int p = 0; p < 2; ++p) {
                    __nv_bfloat162 h2 = *(const __nv_bfloat162*)&hw[p];
                    __nv_bfloat162 l2 = *(const __nv_bfloat162*)&lw[p];
                    Bs[(bk*4 + 2*p)     * 65 + brow] =
                        __bfloat162float(__low2bfloat16(h2)) +
                        __bfloat162float(__low2bfloat16(l2));
                    Bs[(bk*4 + 2*p + 1) * 65 + brow] =
                        __bfloat162float(__high2bfloat16(h2)) +
                        __bfloat162float(__high2bfloat16(l2));
                }
            }
            __syncthreads();
            #pragma unroll
            for (int k = 0; k < 16; ++k) {
                float av[8], bv[4];
                #pragma unroll
                for (int i = 0; i < 8; ++i) av[i] = As[k * 129 + tr8 + i];
                #pragma unroll
                for (int j = 0; j < 4; ++j) bv[j] = Bs[k * 65 + tc4 + j];
                #pragma unroll
                for (int i = 0; i < 8; ++i)
                    #pragma unroll
                    for (int j = 0; j < 4; ++j)
                        acc[i][j] += av[i] * bv[j];
            }
        }

        #pragma unroll
        for (int i = 0; i < 8; ++i) {
            const int row = bm + tr8 + i;
            #pragma unroll
            for (int j = 0; j < 4; j += 2) {
                const int col = bn + tc4 + j;
                float vx = acc[i][j], vy = acc[i][j+1];
                if (HASBIAS) { vx += bias[col]; vy += bias[col + 1]; }
                if (RELU)    { vx = fmaxf(vx, 0.f); vy = fmaxf(vy, 0.f); }
                if (QSCALEZ > 0 && qscale) { vx *= INV_TEMPER; vy *= INV_TEMPER; }
                if (SPLIT) {
                    uint32_t hw, lw;
                    packsplit(vx, vy, hw, lw);
                    *(uint32_t*)(Chi + (long)row * N + col) = hw;
                    *(uint32_t*)(Clo + (long)row * N + col) = lw;
                } else {
                    float2 f = { vx, vy };
                    *(float2*)(C + (long)row * N + col) = f;
                }
            }
        }
        return;
    }

    // ---------------- HMMA path (tensor pipe) -----------------------------
    const int lane = tid & 31, warp = tid >> 5;
    const int wm = (warp & 1) * 64, wn = (warp >> 1) * 16;
    const uint32_t sbase = (uint32_t)__cvta_generic_to_shared(sm);

    const int arow = tid >> 1, acb = (tid & 1) * 2;
    const int brow = tid >> 2, bcb = tid & 3;
    const long aoff = (long)(bm + arow) * K;
    const long boff = (long)(bn + brow) * K;
    const uint32_t ad0 = swoff(arow, acb), ad1 = swoff(arow, acb + 1);
    const uint32_t bd0 = swoff(brow, bcb);

    auto issue = [&](int slot, int k0) {
        const uint32_t s = sbase + slot * 24576;
        cpa16(s + ad0,         Ah + aoff + k0 + acb*8);
        cpa16(s + ad1,         Ah + aoff + k0 + acb*8 + 8);
        cpa16(s + 8192 + ad0,  Al + aoff + k0 + acb*8);
        cpa16(s + 8192 + ad1,  Al + aoff + k0 + acb*8 + 8);
        cpa16(s + 16384 + bd0, Bh + boff + k0 + bcb*8);
        cpa16(s + 20480 + bd0, Bl + boff + k0 + bcb*8);
    };

    float acc[4][2][4];
    #pragma unroll
    for (int mt = 0; mt < 4; ++mt)
        #pragma unroll
        for (int n2 = 0; n2 < 2; ++n2)
            #pragma unroll
            for (int j = 0; j < 4; ++j) acc[mt][n2][j] = 0.f;

    issue(0, 0);  cpa_commit();
    issue(1, 32); cpa_commit();

    const int nt = K / 32;
    #pragma unroll 1
    for (int t = 0; t < nt; ++t) {
        cpa_wait<1>();
        __syncthreads();
        const uint32_t aH = sbase + (t % 3) * 24576;
        const uint32_t aL = aH + 8192;
        const uint32_t bH = aH + 16384;
        const uint32_t bL = aH + 20480;
        #pragma unroll
        for (int kk = 0; kk < 2; ++kk) {
            const int kc = kk * 2 + (lane >> 4);
            const int br = wn + (lane & 15);
            uint32_t bhf[4], blf[4];
            ldsm4(bhf, bH + swoff(br, kc));
            ldsm4(blf, bL + swoff(br, kc));
            #pragma unroll
            for (int mt = 0; mt < 4; ++mt) {
                const int ar = wm + mt * 16 + (lane & 15);
                uint32_t ahf[4], alf[4];
                ldsm4(ahf, aH + swoff(ar, kc));
                ldsm4(alf, aL + swoff(ar, kc));
                #pragma unroll
                for (int n2 = 0; n2 < 2; ++n2) {
                    mma_bf16(acc[mt][n2], ahf, bhf[n2], bhf[n2 + 2]);
                    mma_bf16(acc[mt][n2], ahf, blf[n2], blf[n2 + 2]);
                    mma_bf16(acc[mt][n2], alf, bhf[n2], bhf[n2 + 2]);
                }
            }
        }
        if (t + 2 < nt) issue((t + 2) % 3, (t + 2) * 32);
        cpa_commit();
    }

    #pragma unroll
    for (int mt = 0; mt < 4; ++mt) {
        const int r0 = bm + wm + mt * 16 + (lane >> 2);
        #pragma unroll
        for (int n2 = 0; n2 < 2; ++n2) {
            const int col = bn + wn + n2 * 8 + (lane & 3) * 2;
            float2 v0 = { acc[mt][n2][0], acc[mt][n2][1] };
            float2 v1 = { acc[mt][n2][2], acc[mt][n2][3] };
            if (HASBIAS) {
                float b0 = bias[col], b1 = bias[col + 1];
                v0.x += b0; v0.y += b1; v1.x += b0; v1.y += b1;
            }
            if (RELU) {
                v0.x = fmaxf(v0.x, 0.f); v0.y = fmaxf(v0.y, 0.f);
                v1.x = fmaxf(v1.x, 0.f); v1.y = fmaxf(v1.y, 0.f);
            }
            if (QSCALEZ > 0 && qscale) {
                v0.x *= INV_TEMPER; v0.y *= INV_TEMPER;
                v1.x *= INV_TEMPER; v1.y *= INV_TEMPER;
            }
            if (SPLIT) {
                bf16 h0, l0, h1, l1, h2, l2, h3, l3;
                split1(v0.x, h0, l0); split1(v0.y, h1, l1);
                split1(v1.x, h2, l2); split1(v1.y, h3, l3);
                *(uint32_t*)(Chi + (long)r0 * N + col)       = pack_bf16(h0, h1);
                *(uint32_t*)(Chi + (long)(r0 + 8) * N + col) = pack_bf16(h2, h3);
                *(uint32_t*)(Clo + (long)r0 * N + col)       = pack_bf16(l0, l1);
                *(uint32_t*)(Clo + (long)(r0 + 8) * N + col) = pack_bf16(l2, l3);
            } else {
                *(float2*)(C + (long)r0 * N + col) = v0;
                *(float2*)(C + (long)(r0 + 8) * N + col) = v1;
            }
        }
    }
}

// ------------------------- FA2 tensor-core attention (R9 best) ------------
// 128 threads (4 warps), q-tile 64 rows, K/V chunks of 64 rows.
// smem: 2 stages x 32KB + Qh 8K + Ql 8K = 80KB -> 2 CTAs/SM.
// Q planes arrive pre-scaled by 1/temper (QKV-GEMM epilogue).
#define FA_SMEM 81920
#define FA_STAGE 32768
#define ST_KH 0
#define ST_KL 8192
#define ST_VH 16384
#define ST_VL 24576
#define FA_QH 65536
#define FA_QL 73728

__global__ __launch_bounds__(128, 2)
void fa2_kernel(const bf16* __restrict__ QKVh,
                const bf16* __restrict__ QKVl,
                float* __restrict__ O)
{
    extern __shared__ uint8_t sm[];
    const uint32_t sbase = (uint32_t)__cvta_generic_to_shared(sm);

    const int h = blockIdx.z, b = blockIdx.y;
    const int q0 = blockIdx.x * 64;
    const int tid = threadIdx.x, lane = tid & 31, warp = tid >> 5;

    const long planeQ = ((long)h * NTOK + (long)b * SEQ) * DHEAD;
    const long planeK = ((long)(NHEAD + h) * NTOK + (long)b * SEQ) * DHEAD;
    const long planeV = ((long)(2*NHEAD + h) * NTOK + (long)b * SEQ) * DHEAD;

    int crow[4], cc16[4];
    #pragma unroll
    for (int p = 0; p < 4; ++p) {
        int ci = tid + p * 128;
        crow[p] = ci >> 3; cc16[p] = ci & 7;
    }

    #pragma unroll
    for (int p = 0; p < 4; ++p) {
        const uint32_t so = swz128(crow[p], cc16[p]);
        const long ro = (long)(q0 + crow[p]) * 64 + cc16[p] * 8;
        cpa16(sbase + FA_QH + so, QKVh + planeQ + ro);
        cpa16(sbase + FA_QL + so, QKVl + planeQ + ro);
    }
    cpa_commit();
    #pragma unroll
    for (int p = 0; p < 4; ++p) {
        const long ro = (long)crow[p] * 64 + cc16[p] * 8;
        const uint32_t so = swz128(crow[p], cc16[p]);
        cpa16(sbase + ST_KH + so, QKVh + planeK + ro);
        cpa16(sbase + ST_KL + so, QKVl + planeK + ro);
        cpa16(sbase + ST_VH + so, QKVh + planeV + ro);
        cpa16(sbase + ST_VL + so, QKVl + planeV + ro);
    }
    cpa_commit();

    cpa_wait<1>();
    __syncthreads();

    uint32_t qh[4][4], ql[4][4];
    {
        const int qrow = warp * 16 + (lane & 15);
        #pragma unroll
        for (int ks = 0; ks < 4; ++ks) {
            ldsm4(qh[ks], sbase + FA_QH + swz128(qrow, 2*ks + (lane >> 4)));
            ldsm4(ql[ks], sbase + FA_QL + swz128(qrow, 2*ks + (lane >> 4)));
        }
    }

    float o[8][4];
    #pragma unroll
    for (int vt = 0; vt < 8; ++vt)
        #pragma unroll
        for (int j = 0; j < 4; ++j) o[vt][j] = 0.f;
    float run_m0 = -INFINITY, run_m1 = -INFINITY;
    float run_l0 = 0.f, run_l1 = 0.f;

    #pragma unroll 1
    for (int c = 0; c < 16; ++c) {
        const uint32_t stg = sbase + (c & 1) * FA_STAGE;
        if (c < 15) {
            const uint32_t nst = sbase + ((c + 1) & 1) * FA_STAGE;
            const long m0 = (long)(c + 1) * 64;
            #pragma unroll
            for (int p = 0; p < 4; ++p) {
                const long ro = (m0 + crow[p]) * 64 + cc16[p] * 8;
                const uint32_t so = swz128(crow[p], cc16[p]);
                cpa16(nst + ST_KH + so, QKVh + planeK + ro);
                cpa16(nst + ST_KL + so, QKVl + planeK + ro);
                cpa16(nst + ST_VH + so, QKVh + planeV + ro);
                cpa16(nst + ST_VL + so, QKVl + planeV + ro);
            }
            cpa_commit();
            cpa_wait<1>();
        } else {
            cpa_wait<0>();
        }
        __syncthreads();

        float s[8][4];
        #pragma unroll
        for (int t = 0; t < 8; ++t)
            #pragma unroll
            for (int j = 0; j < 4; ++j) s[t][j] = 0.f;
        #pragma unroll
        for (int g = 0; g < 4; ++g) {
            const int krow = g * 16 + (lane & 15);
            #pragma unroll
            for (int ks = 0; ks < 4; ++ks) {
                const uint32_t so = swz128(krow, 2*ks + (lane >> 4));
                uint32_t khf[4], klf[4];
                ldsm4(khf, stg + ST_KH + so);
                ldsm4(klf, stg + ST_KL + so);
                #pragma unroll
                for (int n2 = 0; n2 < 2; ++n2) {
                    float* st = s[g*2 + n2];
                    mma_bf16(st, qh[ks], khf[n2], khf[n2 + 2]);
                    mma_bf16(st, qh[ks], klf[n2], klf[n2 + 2]);
                    mma_bf16(st, ql[ks], khf[n2], khf[n2 + 2]);
                }
            }
        }

        float mx0 = -INFINITY, mx1 = -INFINITY;
        #pragma unroll
        for (int t = 0; t < 8; ++t) {
            mx0 = fmaxf(mx0, fmaxf(s[t][0], s[t][1]));
            mx1 = fmaxf(mx1, fmaxf(s[t][2], s[t][3]));
        }
        mx0 = fmaxf(mx0, __shfl_xor_sync(0xffffffffu, mx0, 1));
        mx0 = fmaxf(mx0, __shfl_xor_sync(0xffffffffu, mx0, 2));
        mx1 = fmaxf(mx1, __shfl_xor_sync(0xffffffffu, mx1, 1));
        mx1 = fmaxf(mx1, __shfl_xor_sync(0xffffffffu, mx1, 2));

        const float nm0 = fmaxf(run_m0, mx0);
        const float nm1 = fmaxf(run_m1, mx1);
        const float sc0 = __expf(run_m0 - nm0);
        const float sc1 = __expf(run_m1 - nm1);
        run_m0 = nm0; run_m1 = nm1;

        float ps0 = 0.f, ps1 = 0.f;
        #pragma unroll
        for (int t = 0; t < 8; ++t) {
            float p0 = __expf(s[t][0] - nm0); s[t][0] = p0;
            float p1 = __expf(s[t][1] - nm0); s[t][1] = p1;
            float p2 = __expf(s[t][2] - nm1); s[t][2] = p2;
            float p3 = __expf(s[t][3] - nm1); s[t][3] = p3;
            ps0 += p0 + p1; ps1 += p2 + p3;
        }
        run_l0 = run_l0 * sc0 + ps0;
        run_l1 = run_l1 * sc1 + ps1;
        #pragma unroll
        for (int vt = 0; vt < 8; ++vt) {
            o[vt][0] *= sc0; o[vt][1] *= sc0;
            o[vt][2] *= sc1; o[vt][3] *= sc1;
        }

        #pragma unroll
        for (int ks = 0; ks < 4; ++ks) {
            uint32_t ah[4], al[4];
            packsplit(s[2*ks][0],   s[2*ks][1],   ah[0], al[0]);
            packsplit(s[2*ks][2],   s[2*ks][3],   ah[1], al[1]);
            packsplit(s[2*ks+1][0], s[2*ks+1][1], ah[2], al[2]);
            packsplit(s[2*ks+1][2], s[2*ks+1][3], ah[3], al[3]);
            const int vrow = ks * 16 + (lane & 15);
            #pragma unroll
            for (int vg = 0; vg < 4; ++vg) {
                const uint32_t so = swz128(vrow, vg*2 + (lane >> 4));
                uint32_t vhf[4], vlf[4];
                ldsm4t(vhf, stg + ST_VH + so);
                ldsm4t(vlf, stg + ST_VL + so);
                #pragma unroll
                for (int n2 = 0; n2 < 2; ++n2) {
                    float* ot = o[vg*2 + n2];
                    mma_bf16(ot, ah, vhf[2*n2], vhf[2*n2 + 1]);
                    mma_bf16(ot, ah, vlf[2*n2], vlf[2*n2 + 1]);
                    mma_bf16(ot, al, vhf[2*n2], vhf[2*n2 + 1]);
                }
            }
        }
        __syncthreads();
    }

    run_l0 += __shfl_xor_sync(0xffffffffu, run_l0, 1);
    run_l0 += __shfl_xor_sync(0xffffffffu, run_l0, 2);
    run_l1 += __shfl_xor_sync(0xffffffffu, run_l1, 1);
    run_l1 += __shfl_xor_sync(0xffffffffu, run_l1, 2);
    const float inv0 = 1.f / run_l0, inv1 = 1.f / run_l1;

    const int r  = q0 + warp * 16 + (lane >> 2);
    const int cb = h * 64 + (lane & 3) * 2;
    #pragma unroll
    for (int vt = 0; vt < 8; ++vt) {
        float2 v0 = { o[vt][0] * inv0, o[vt][1] * inv0 };
        float2 v1 = { o[vt][2] * inv1, o[vt][3] * inv1 };
        *(float2*)(O + ((long)b*SEQ + r)     * DMODEL + cb + vt*8) = v0;
        *(float2*)(O + ((long)b*SEQ + r + 8) * DMODEL + cb + vt*8) = v1;
    }
}

// ------------------------- residual + LayerNorm (+ split planes) ----------
__global__ void ln_kernel(const float* __restrict__ X, const float* __restrict__ R,
                          const float* __restrict__ gamma, const float* __restrict__ beta,
                          float* __restrict__ Y,
                          bf16* __restrict__ Yh, bf16* __restrict__ Yl)
{
    const long row = blockIdx.x;
    const int tid = threadIdx.x;
    __shared__ float red[128];
    const int i = tid * 4;
    float4 a = *(const float4*)(X + row*DMODEL + i);
    float4 b = *(const float4*)(R + row*DMODEL + i);
    float z0 = a.x + b.x, z1 = a.y + b.y, z2 = a.z + b.z, z3 = a.w + b.w;

    red[tid] = z0 + z1 + z2 + z3; __syncthreads();
    for (int s = 64; s > 0; s >>= 1) {
        if (tid < s) red[tid] += red[tid+s];
        __syncthreads();
    }
    float mu = red[0] * (1.f / DMODEL); __syncthreads();

    float d0 = z0-mu, d1 = z1-mu, d2 = z2-mu, d3 = z3-mu;
    red[tid] = d0*d0 + d1*d1 + d2*d2 + d3*d3; __syncthreads();
    for (int s = 64; s > 0; s >>= 1) {
        if (tid < s) red[tid] += red[tid+s];
        __syncthreads();
    }
    float sigma = sqrtf(red[0] * (1.f / (DMODEL - 1)));   // unbiased (ddof=1)
    float sc = 1.f / (sigma + EPS);

    float4 g4 = *(const float4*)(gamma + i);
    float4 be = *(const float4*)(beta + i);
    float4 y;
    y.x = d0 * sc * g4.x + be.x;
    y.y = d1 * sc * g4.y + be.y;
    y.z = d2 * sc * g4.z + be.z;
    y.w = d3 * sc * g4.w + be.w;
    *(float4*)(Y + row*DMODEL + i) = y;

    bf16 h0,l0,h1,l1,h2,l2,h3,l3;
    split1(y.x,h0,l0); split1(y.y,h1,l1); split1(y.z,h2,l2); split1(y.w,h3,l3);
    *(uint2*)(Yh + row*DMODEL + i) = make_uint2(pack_bf16(h0,h1), pack_bf16(h2,h3));
    *(uint2*)(Yl + row*DMODEL + i) = make_uint2(pack_bf16(l0,l1), pack_bf16(l2,l3));
}

// ------------------------- launch ------------------------------------------
extern "C" void kernel_launch(void* const* d_in, const int* in_sizes, int n_in,
                              void* d_out, int out_size)
{
    (void)in_sizes; (void)n_in; (void)out_size;
    const float* x    = (const float*)d_in[0];
    const float* pos  = (const float*)d_in[1];
    const float* wq   = (const float*)d_in[2];
    const float* wk   = (const float*)d_in[3];
    const float* wv   = (const float*)d_in[4];
    const float* ln1a = (const float*)d_in[5];
    const float* ln1b = (const float*)d_in[6];
    const float* w1   = (const float*)d_in[7];
    const float* b1   = (const float*)d_in[8];
    const float* w2   = (const float*)d_in[9];
    const float* b2   = (const float*)d_in[10];
    const float* ln2a = (const float*)d_in[11];
    const float* ln2b = (const float*)d_in[12];
    float* out = (float*)d_out;

    float *gx, *ga, *go;
    bf16 *xh, *xl, *hh, *hl, *wqkvh, *wqkvl, *w1h, *w1l, *w2h, *w2l, *qkvh, *qkvl;
    cudaGetSymbolAddress((void**)&gx, g_x);
    cudaGetSymbolAddress((void**)&ga, g_att);
    cudaGetSymbolAddress((void**)&go, g_o);
    cudaGetSymbolAddress((void**)&xh, g_xh);
    cudaGetSymbolAddress((void**)&xl, g_xl);
    cudaGetSymbolAddress((void**)&hh, g_hh);
    cudaGetSymbolAddress((void**)&hl, g_hl);
    cudaGetSymbolAddress((void**)&wqkvh, g_wqkvh);
    cudaGetSymbolAddress((void**)&wqkvl, g_wqkvl);
    cudaGetSymbolAddress((void**)&w1h, g_w1h);
    cudaGetSymbolAddress((void**)&w1l, g_w1l);
    cudaGetSymbolAddress((void**)&w2h, g_w2h);
    cudaGetSymbolAddress((void**)&w2l, g_w2l);
    cudaGetSymbolAddress((void**)&qkvh, g_qkv_h);
    cudaGetSymbolAddress((void**)&qkvl, g_qkv_l);

    static bool attr_set = false;
    if (!attr_set) {
        cudaFuncSetAttribute(fa2_kernel,
                             cudaFuncAttributeMaxDynamicSharedMemorySize, FA_SMEM);
        cudaFuncSetAttribute(mma_gemm_bf<8,false,false,true>,
                             cudaFuncAttributeMaxDynamicSharedMemorySize, GEMM_SMEM);
        cudaFuncSetAttribute(mma_gemm_bf<0,true,true,true>,
                             cudaFuncAttributeMaxDynamicSharedMemorySize, GEMM_SMEM);
        cudaFuncSetAttribute(mma_gemm_bf<0,false,true,false>,
                             cudaFuncAttributeMaxDynamicSharedMemorySize, GEMM_SMEM);
        attr_set = true;
    }

    // prep: positional add (+ split), weight transpose/split
    add_pos_kernel<<<NTOK*DMODEL/512, 512>>>(x, pos, gx, xh, xl);
    transpose3_kernel<<<dim3(DHEAD/32, DMODEL/32, 3*NLAYERS*NHEAD), dim3(32,8)>>>(
        wq, wk, wv, wqkvh, wqkvl);
    split_kernel<<<NLAYERS*DINNER*DMODEL/1024, 256>>>(w1, w1h, w1l, NLAYERS*DINNER*DMODEL);
    split_kernel<<<NLAYERS*DMODEL*DINNER/1024, 256>>>(w2, w2h, w2l, NLAYERS*DMODEL*DINNER);

    const long wqkv_mat   = (long)DHEAD * DMODEL;
    const long wqkv_layer = 3L * NHEAD * wqkv_mat;
    const long qkv_mat    = (long)NTOK * DHEAD;

    for (int i = 0; i < NLAYERS; ++i) {
        // fused QKV: 24 mats [4096,512]x[64,512]^T -> split planes.
        // z<8 = Q heads pre-scaled; z>=21 (3 V heads) run on the SIMT/FMA path.
        mma_gemm_bf<8,false,false,true><<<dim3(1, NTOK/128, 3*NHEAD), 256, GEMM_SMEM>>>(
            xh, xl, wqkvh + i*wqkv_layer, wqkvl + i*wqkv_layer,
            nullptr, nullptr, qkvh, qkvl,
            NTOK, DHEAD, DMODEL, wqkv_mat, qkv_mat, 999, 21);

        fa2_kernel<<<dim3(SEQ/64, BATCH, NHEAD), 128, FA_SMEM>>>(qkvh, qkvl, ga);

        ln_kernel<<<NTOK, 128>>>(ga, gx, ln1a + i*DMODEL, ln1b + i*DMODEL, gx, xh, xl);

        // FFN1: h = relu(x @ w1^T + b1) -> split planes; last 2 N-tiles SIMT
        mma_gemm_bf<0,true,true,true><<<dim3(DINNER/64, NTOK/128, 1), 256, GEMM_SMEM>>>(
            xh, xl, w1h + (long)i*DINNER*DMODEL, w1l + (long)i*DINNER*DMODEL,
            nullptr, b1 + i*DINNER, hh, hl,
            NTOK, DINNER, DMODEL, 0, 0, 14, 999);
        // FFN2: o = h @ w2^T + b2 -> fp32; last N-tile SIMT
        mma_gemm_bf<0,false,true,false><<<dim3(DMODEL/64, NTOK/128, 1), 256, GEMM_SMEM>>>(
            hh, hl, w2h + (long)i*DMODEL*DINNER, w2l + (long)i*DMODEL*DINNER,
            go, b2 + i*DMODEL, nullptr, nullptr,
            NTOK, DMODEL, DINNER, 0, 0, 7, 999);

        ln_kernel<<<NTOK, 128>>>(go, gx, ln2a + i*DMODEL, ln2b + i*DMODEL, gx, xh, xl);
    }

    cudaMemcpyAsync(out, gx, (size_t)NTOK*DMODEL*sizeof(float),
                    cudaMemcpyDeviceToDevice);
}

// round 15
// speedup vs baseline: 1.5580x; 1.5580x over previous
#include <cuda_runtime.h>
#include <cuda_bf16.h>
#include <math.h>
#include <stdint.h>

#define BATCH 4
#define SEQ 1024
#define DMODEL 512
#define NHEAD 8
#define DHEAD 64
#define DINNER 1024
#define NLAYERS 2
#define NTOK (BATCH*SEQ)          // 4096
#define EPS 1e-3f
#define INV_TEMPER 0.044194173824159216f   // 1/sqrt(512)

typedef __nv_bfloat16 bf16;

// ------------------------- scratch (device globals; no runtime alloc) -----
__device__ float g_x  [NTOK*DMODEL];       // fp32 activations (residual path)
__device__ float g_att[NTOK*DMODEL];
__device__ float g_o  [NTOK*DMODEL];
__device__ bf16 g_xh[NTOK*DMODEL],  g_xl[NTOK*DMODEL];
__device__ bf16 g_hh[NTOK*DINNER],  g_hl[NTOK*DINNER];
__device__ bf16 g_wqkvh[NLAYERS*3*NHEAD*DHEAD*DMODEL];
__device__ bf16 g_wqkvl[NLAYERS*3*NHEAD*DHEAD*DMODEL];
__device__ bf16 g_w1h[NLAYERS*DINNER*DMODEL], g_w1l[NLAYERS*DINNER*DMODEL];
__device__ bf16 g_w2h[NLAYERS*DMODEL*DINNER], g_w2l[NLAYERS*DMODEL*DINNER];
__device__ bf16 g_qkv_h[3*NHEAD*NTOK*DHEAD];
__device__ bf16 g_qkv_l[3*NHEAD*NTOK*DHEAD];

// ------------------------- small helpers ----------------------------------
__device__ __forceinline__ uint32_t pack_bf16(bf16 a, bf16 b)
{
    __nv_bfloat162 t = __halves2bfloat162(a, b);
    return *(uint32_t*)&t;
}
__device__ __forceinline__ void split1(float v, bf16& h, bf16& l)
{
    h = __float2bfloat16(v);
    l = __float2bfloat16(v - __bfloat162float(h));
}

// ------------------------- x + pos_enc (fp32 + planes) --------------------
__global__ void add_pos_kernel(const float* __restrict__ x,
                               const float* __restrict__ pos,
                               float* __restrict__ y,
                               bf16* __restrict__ yh, bf16* __restrict__ yl)
{
    int idx = blockIdx.x * 512 + threadIdx.x;
    float v = x[idx] + pos[idx & (SEQ*DMODEL - 1)];
    y[idx] = v;
    bf16 h, l; split1(v, h, l);
    yh[idx] = h; yl[idx] = l;
}

// ------------------------- qkv weight transpose + split -------------------
__global__ void transpose3_kernel(const float* __restrict__ wq,
                                  const float* __restrict__ wk,
                                  const float* __restrict__ wv,
                                  bf16* __restrict__ oh, bf16* __restrict__ ol)
{
    __shared__ float tile[32][33];
    const int z = blockIdx.z;
    const int w = z / (NLAYERS*NHEAD);
    const int l = (z / NHEAD) % NLAYERS;
    const int h = z % NHEAD;
    const float* ip = (w == 0 ? wq : w == 1 ? wk : wv)
                      + (long)(l*NHEAD + h) * DMODEL * DHEAD;
    const long ob = (long)((l*3 + w)*NHEAD + h) * DHEAD * DMODEL;
    int c0 = blockIdx.x * 32, r0 = blockIdx.y * 32;
    for (int i = threadIdx.y; i < 32; i += 8)
        tile[i][threadIdx.x] = ip[(long)(r0 + i) * DHEAD + c0 + threadIdx.x];
    __syncthreads();
    for (int i = threadIdx.y; i < 32; i += 8) {
        float v = tile[threadIdx.x][i];
        bf16 hh, ll; split1(v, hh, ll);
        long o = ob + (long)(c0 + i) * DMODEL + r0 + threadIdx.x;
        oh[o] = hh; ol[o] = ll;
    }
}

// ------------------------- generic fp32 -> split planes -------------------
__global__ void split_kernel(const float* __restrict__ in,
                             bf16* __restrict__ oh, bf16* __restrict__ ol, int n)
{
    int idx = (blockIdx.x * 256 + threadIdx.x) * 4;
    if (idx >= n) return;
    float4 v = *(const float4*)(in + idx);
    bf16 h0,l0,h1,l1,h2,l2,h3,l3;
    split1(v.x,h0,l0); split1(v.y,h1,l1); split1(v.z,h2,l2); split1(v.w,h3,l3);
    *(uint2*)(oh + idx) = make_uint2(pack_bf16(h0,h1), pack_bf16(h2,h3));
    *(uint2*)(ol + idx) = make_uint2(pack_bf16(l0,l1), pack_bf16(l2,l3));
}

// ------------------------- mma / ldsm / cp.async helpers ------------------
__device__ __forceinline__ void ldsm4(uint32_t* r, uint32_t addr)
{
    asm volatile("ldmatrix.sync.aligned.m8n8.x4.shared.b16 {%0,%1,%2,%3}, [%4];"
        : "=r"(r[0]), "=r"(r[1]), "=r"(r[2]), "=r"(r[3]) : "r"(addr));
}
__device__ __forceinline__ void ldsm4t(uint32_t* r, uint32_t addr)
{
    asm volatile("ldmatrix.sync.aligned.m8n8.x4.trans.shared.b16 {%0,%1,%2,%3}, [%4];"
        : "=r"(r[0]), "=r"(r[1]), "=r"(r[2]), "=r"(r[3]) : "r"(addr));
}
__device__ __forceinline__ void mma_bf16(float* c, const uint32_t* a,
                                         uint32_t b0, uint32_t b1)
{
    asm volatile(
        "mma.sync.aligned.m16n8k16.row.col.f32.bf16.bf16.f32 "
        "{%0,%1,%2,%3}, {%4,%5,%6,%7}, {%8,%9}, {%0,%1,%2,%3};\n"
        : "+f"(c[0]), "+f"(c[1]), "+f"(c[2]), "+f"(c[3])
        : "r"(a[0]), "r"(a[1]), "r"(a[2]), "r"(a[3]), "r"(b0), "r"(b1));
}
__device__ __forceinline__ void packsplit(float x, float y, uint32_t& hi, uint32_t& lo)
{
    bf16 hx = __float2bfloat16(x), hy = __float2bfloat16(y);
    hi = pack_bf16(hx, hy);
    lo = pack_bf16(__float2bfloat16(x - __bfloat162float(hx)),
                   __float2bfloat16(y - __bfloat162float(hy)));
}
__device__ __forceinline__ void cpa16(uint32_t dst, const void* src)
{
    asm volatile("cp.async.cg.shared.global [%0], [%1], 16;\n" :: "r"(dst), "l"(src));
}
__device__ __forceinline__ void cpa_commit()
{
    asm volatile("cp.async.commit_group;\n");
}
template<int N> __device__ __forceinline__ void cpa_wait()
{
    asm volatile("cp.async.wait_group %0;\n" :: "n"(N));
}
// GEMM smem swizzle: 64B rows (32 bf16), 4x16B chunks
__device__ __forceinline__ int swoff(int row, int chunk)
{
    return row * 64 + ((chunk ^ ((row >> 1) & 3)) * 16);
}
// attention plane swizzle: 128B rows (64 bf16), 8x16B chunks
__device__ __forceinline__ uint32_t swz128(int row, int c16)
{
    return (uint32_t)(row * 128 + ((c16 ^ (row & 7)) * 16));
}

// ------------------------- split-bf16 tensor-core GEMM (NT) ----------------
// C = A * B^T; A,B given as hi/lo bf16 planes (row-major, K contiguous).
// BM=128, BN=64, BK=32, 256 thr, 3-stage cp.async pipeline.
// QSCALEZ: blocks with blockIdx.z < QSCALEZ scale output by 1/temper.
#define GEMM_SMEM 73728

template<int QSCALEZ, bool RELU, bool HASBIAS, bool SPLIT>
__global__ __launch_bounds__(256, 2)
void mma_gemm_bf(const bf16* __restrict__ Ah, const bf16* __restrict__ Al,
                 const bf16* __restrict__ Bh, const bf16* __restrict__ Bl,
                 float* __restrict__ C, const float* __restrict__ bias,
                 bf16* __restrict__ Chi, bf16* __restrict__ Clo,
                 int M, int N, int K, long strideB, long strideC)
{
    extern __shared__ uint8_t sm[];
    Bh += (long)blockIdx.z * strideB;
    Bl += (long)blockIdx.z * strideB;
    if (SPLIT) { Chi += (long)blockIdx.z * strideC; Clo += (long)blockIdx.z * strideC; }
    else       { C   += (long)blockIdx.z * strideC; }
    const int bm = blockIdx.y * 128, bn = blockIdx.x * 64;
    const int tid = threadIdx.x, lane = tid & 31, warp = tid >> 5;
    const int wm = (warp & 1) * 64, wn = (warp >> 1) * 16;
    const uint32_t sbase = (uint32_t)__cvta_generic_to_shared(sm);

    const int arow = tid >> 1, acb = (tid & 1) * 2;
    const int brow = tid >> 2, bcb = tid & 3;
    const long aoff = (long)(bm + arow) * K;
    const long boff = (long)(bn + brow) * K;
    const uint32_t ad0 = swoff(arow, acb), ad1 = swoff(arow, acb + 1);
    const uint32_t bd0 = swoff(brow, bcb);

    auto issue = [&](int slot, int k0) {
        const uint32_t s = sbase + slot * 24576;
        cpa16(s + ad0,         Ah + aoff + k0 + acb*8);
        cpa16(s + ad1,         Ah + aoff + k0 + acb*8 + 8);
        cpa16(s + 8192 + ad0,  Al + aoff + k0 + acb*8);
        cpa16(s + 8192 + ad1,  Al + aoff + k0 + acb*8 + 8);
        cpa16(s + 16384 + bd0, Bh + boff + k0 + bcb*8);
        cpa16(s + 20480 + bd0, Bl + boff + k0 + bcb*8);
    };

    float acc[4][2][4];
    #pragma unroll
    for (int mt = 0; mt < 4; ++mt)
        #pragma unroll
        for (int n2 = 0; n2 < 2; ++n2)
            #pragma unroll
            for (int j = 0; j < 4; ++j) acc[mt][n2][j] = 0.f;

    issue(0, 0);  cpa_commit();
    issue(1, 32); cpa_commit();

    const int nt = K / 32;
    #pragma unroll 1
    for (int t = 0; t < nt; ++t) {
        cpa_wait<1>();
        __syncthreads();
        const uint32_t aH = sbase + (t % 3) * 24576;
        const uint32_t aL = aH + 8192;
        const uint32_t bH = aH + 16384;
        const uint32_t bL = aH + 20480;
        #pragma unroll
        for (int kk = 0; kk < 2; ++kk) {
            const int kc = kk * 2 + (lane >> 4);
            const int br = wn + (lane & 15);
            uint32_t bhf[4], blf[4];
            ldsm4(bhf, bH + swoff(br, kc));
            ldsm4(blf, bL + swoff(br, kc));
            #pragma unroll
            for (int mt = 0; mt < 4; ++mt) {
                const int ar = wm + mt * 16 + (lane & 15);
                uint32_t ahf[4], alf[4];
                ldsm4(ahf, aH + swoff(ar, kc));
                ldsm4(alf, aL + swoff(ar, kc));
                #pragma unroll
                for (int n2 = 0; n2 < 2; ++n2) {
                    mma_bf16(acc[mt][n2], ahf, bhf[n2], bhf[n2 + 2]);
                    mma_bf16(acc[mt][n2], ahf, blf[n2], blf[n2 + 2]);
                    mma_bf16(acc[mt][n2], alf, bhf[n2], bhf[n2 + 2]);
                }
            }
        }
        if (t + 2 < nt) issue((t + 2) % 3, (t + 2) * 32);
        cpa_commit();
    }

    const bool qscale = (QSCALEZ > 0) && ((int)blockIdx.z < QSCALEZ);
    #pragma unroll
    for (int mt = 0; mt < 4; ++mt) {
        const int r0 = bm + wm + mt * 16 + (lane >> 2);
        #pragma unroll
        for (int n2 = 0; n2 < 2; ++n2) {
            const int col = bn + wn + n2 * 8 + (lane & 3) * 2;
            float2 v0 = { acc[mt][n2][0], acc[mt][n2][1] };
            float2 v1 = { acc[mt][n2][2], acc[mt][n2][3] };
            if (HASBIAS) {
                float b0 = bias[col], b1 = bias[col + 1];
                v0.x += b0; v0.y += b1; v1.x += b0; v1.y += b1;
            }
            if (RELU) {
                v0.x = fmaxf(v0.x, 0.f); v0.y = fmaxf(v0.y, 0.f);
                v1.x = fmaxf(v1.x, 0.f); v1.y = fmaxf(v1.y, 0.f);
            }
            if (QSCALEZ > 0 && qscale) {
                v0.x *= INV_TEMPER; v0.y *= INV_TEMPER;
                v1.x *= INV_TEMPER; v1.y *= INV_TEMPER;
            }
            if (SPLIT) {
                bf16 h0, l0, h1, l1, h2, l2, h3, l3;
                split1(v0.x, h0, l0); split1(v0.y, h1, l1);
                split1(v1.x, h2, l2); split1(v1.y, h3, l3);
                *(uint32_t*)(Chi + (long)r0 * N + col)       = pack_bf16(h0, h1);
                *(uint32_t*)(Chi + (long)(r0 + 8) * N + col) = pack_bf16(h2, h3);
                *(uint32_t*)(Clo + (long)r0 * N + col)       = pack_bf16(l0, l1);
                *(uint32_t*)(Clo + (long)(r0 + 8) * N + col) = pack_bf16(l2, l3);
            } else {
                *(float2*)(C + (long)r0 * N + col) = v0;
                *(float2*)(C + (long)(r0 + 8) * N + col) = v1;
            }
        }
    }
}

// ------------------------- FA2 tensor-core attention ----------------------
// R9 structure (64-row q tile, 128 thr, occ 2). PV uses 2 terms:
// O += Ph*Vh + Ph*Vl  (P in [0,1]; bf16 P carries full 2^-9 relative accuracy;
// the dropped Pl*Vh term is ~2e-4 absolute in O and washed by residual+LN).
#define FA_SMEM 81920
#define FA_STAGE 32768
#define ST_KH 0
#define ST_KL 8192
#define ST_VH 16384
#define ST_VL 24576
#define FA_QH 65536
#define FA_QL 73728

__global__ __launch_bounds__(128, 2)
void fa2_kernel(const bf16* __restrict__ QKVh,
                const bf16* __restrict__ QKVl,
                float* __restrict__ O)
{
    extern __shared__ uint8_t sm[];
    const uint32_t sbase = (uint32_t)__cvta_generic_to_shared(sm);

    const int h = blockIdx.z, b = blockIdx.y;
    const int q0 = blockIdx.x * 64;
    const int tid = threadIdx.x, lane = tid & 31, warp = tid >> 5;

    const long planeQ = ((long)h * NTOK + (long)b * SEQ) * DHEAD;
    const long planeK = ((long)(NHEAD + h) * NTOK + (long)b * SEQ) * DHEAD;
    const long planeV = ((long)(2*NHEAD + h) * NTOK + (long)b * SEQ) * DHEAD;

    int crow[4], cc16[4];
    #pragma unroll
    for (int p = 0; p < 4; ++p) {
        int ci = tid + p * 128;
        crow[p] = ci >> 3; cc16[p] = ci & 7;
    }

    #pragma unroll
    for (int p = 0; p < 4; ++p) {
        const uint32_t so = swz128(crow[p], cc16[p]);
        const long ro = (long)(q0 + crow[p]) * 64 + cc16[p] * 8;
        cpa16(sbase + FA_QH + so, QKVh + planeQ + ro);
        cpa16(sbase + FA_QL + so, QKVl + planeQ + ro);
    }
    cpa_commit();
    #pragma unroll
    for (int p = 0; p < 4; ++p) {
        const long ro = (long)crow[p] * 64 + cc16[p] * 8;
        const uint32_t so = swz128(crow[p], cc16[p]);
        cpa16(sbase + ST_KH + so, QKVh + planeK + ro);
        cpa16(sbase + ST_KL + so, QKVl + planeK + ro);
        cpa16(sbase + ST_VH + so, QKVh + planeV + ro);
        cpa16(sbase + ST_VL + so, QKVl + planeV + ro);
    }
    cpa_commit();

    cpa_wait<1>();
    __syncthreads();

    uint32_t qh[4][4], ql[4][4];
    {
        const int qrow = warp * 16 + (lane & 15);
        #pragma unroll
        for (int ks = 0; ks < 4; ++ks) {
            ldsm4(qh[ks], sbase + FA_QH + swz128(qrow, 2*ks + (lane >> 4)));
            ldsm4(ql[ks], sbase + FA_QL + swz128(qrow, 2*ks + (lane >> 4)));
        }
    }

    float o[8][4];
    #pragma unroll
    for (int vt = 0; vt < 8; ++vt)
        #pragma unroll
        for (int j = 0; j < 4; ++j) o[vt][j] = 0.f;
    float run_m0 = -INFINITY, run_m1 = -INFINITY;
    float run_l0 = 0.f, run_l1 = 0.f;

    #pragma unroll 1
    for (int c = 0; c < 16; ++c) {
        const uint32_t stg = sbase + (c & 1) * FA_STAGE;
        if (c < 15) {
            const uint32_t nst = sbase + ((c + 1) & 1) * FA_STAGE;
            const long m0 = (long)(c + 1) * 64;
            #pragma unroll
            for (int p = 0; p < 4; ++p) {
                const long ro = (m0 + crow[p]) * 64 + cc16[p] * 8;
                const uint32_t so = swz128(crow[p], cc16[p]);
                cpa16(nst + ST_KH + so, QKVh + planeK + ro);
                cpa16(nst + ST_KL + so, QKVl + planeK + ro);
                cpa16(nst + ST_VH + so, QKVh + planeV + ro);
                cpa16(nst + ST_VL + so, QKVl + planeV + ro);
            }
            cpa_commit();
            cpa_wait<1>();
        } else {
            cpa_wait<0>();
        }
        __syncthreads();

        // ---- S = Q K^T (split bf16, 3 terms), 8 n8-tiles (64 K rows)
        float s[8][4];
        #pragma unroll
        for (int t = 0; t < 8; ++t)
            #pragma unroll
            for (int j = 0; j < 4; ++j) s[t][j] = 0.f;
        #pragma unroll
        for (int g = 0; g < 4; ++g) {
            const int krow = g * 16 + (lane & 15);
            #pragma unroll
            for (int ks = 0; ks < 4; ++ks) {
                const uint32_t so = swz128(krow, 2*ks + (lane >> 4));
                uint32_t khf[4], klf[4];
                ldsm4(khf, stg + ST_KH + so);
                ldsm4(klf, stg + ST_KL + so);
                #pragma unroll
                for (int n2 = 0; n2 < 2; ++n2) {
                    float* st = s[g*2 + n2];
                    mma_bf16(st, qh[ks], khf[n2], khf[n2 + 2]);
                    mma_bf16(st, qh[ks], klf[n2], klf[n2 + 2]);
                    mma_bf16(st, ql[ks], khf[n2], khf[n2 + 2]);
                }
            }
        }

        // ---- online softmax (rows r = lane>>2, r+8); scores pre-scaled
        float mx0 = -INFINITY, mx1 = -INFINITY;
        #pragma unroll
        for (int t = 0; t < 8; ++t) {
            mx0 = fmaxf(mx0, fmaxf(s[t][0], s[t][1]));
            mx1 = fmaxf(mx1, fmaxf(s[t][2], s[t][3]));
        }
        mx0 = fmaxf(mx0, __shfl_xor_sync(0xffffffffu, mx0, 1));
        mx0 = fmaxf(mx0, __shfl_xor_sync(0xffffffffu, mx0, 2));
        mx1 = fmaxf(mx1, __shfl_xor_sync(0xffffffffu, mx1, 1));
        mx1 = fmaxf(mx1, __shfl_xor_sync(0xffffffffu, mx1, 2));

        const float nm0 = fmaxf(run_m0, mx0);
        const float nm1 = fmaxf(run_m1, mx1);
        const float sc0 = __expf(run_m0 - nm0);
        const float sc1 = __expf(run_m1 - nm1);
        run_m0 = nm0; run_m1 = nm1;

        float ps0 = 0.f, ps1 = 0.f;
        #pragma unroll
        for (int t = 0; t < 8; ++t) {
            float p0 = __expf(s[t][0] - nm0); s[t][0] = p0;
            float p1 = __expf(s[t][1] - nm0); s[t][1] = p1;
            float p2 = __expf(s[t][2] - nm1); s[t][2] = p2;
            float p3 = __expf(s[t][3] - nm1); s[t][3] = p3;
            ps0 += p0 + p1; ps1 += p2 + p3;
        }
        run_l0 = run_l0 * sc0 + ps0;
        run_l1 = run_l1 * sc1 + ps1;
        #pragma unroll
        for (int vt = 0; vt < 8; ++vt) {
            o[vt][0] *= sc0; o[vt][1] *= sc0;
            o[vt][2] *= sc1; o[vt][3] *= sc1;
        }

        // ---- O += P V : 2 terms (Ph*Vh + Ph*Vl)
        #pragma unroll
        for (int ks = 0; ks < 4; ++ks) {
            uint32_t ah[4];
            ah[0] = pack_bf16(__float2bfloat16(s[2*ks][0]),   __float2bfloat16(s[2*ks][1]));
            ah[1] = pack_bf16(__float2bfloat16(s[2*ks][2]),   __float2bfloat16(s[2*ks][3]));
            ah[2] = pack_bf16(__float2bfloat16(s[2*ks+1][0]), __float2bfloat16(s[2*ks+1][1]));
            ah[3] = pack_bf16(__float2bfloat16(s[2*ks+1][2]), __float2bfloat16(s[2*ks+1][3]));
            const int vrow = ks * 16 + (lane & 15);
            #pragma unroll
            for (int vg = 0; vg < 4; ++vg) {
                const uint32_t so = swz128(vrow, vg*2 + (lane >> 4));
                uint32_t vhf[4], vlf[4];
                ldsm4t(vhf, stg + ST_VH + so);
                ldsm4t(vlf, stg + ST_VL + so);
                #pragma unroll
                for (int n2 = 0; n2 < 2; ++n2) {
                    float* ot = o[vg*2 + n2];
                    mma_bf16(ot, ah, vhf[2*n2], vhf[2*n2 + 1]);
                    mma_bf16(ot, ah, vlf[2*n2], vlf[2*n2 + 1]);
                }
            }
        }
        __syncthreads();
    }

    run_l0 += __shfl_xor_sync(0xffffffffu, run_l0, 1);
    run_l0 += __shfl_xor_sync(0xffffffffu, run_l0, 2);
    run_l1 += __shfl_xor_sync(0xffffffffu, run_l1, 1);
    run_l1 += __shfl_xor_sync(0xffffffffu, run_l1, 2);
    const float inv0 = 1.f / run_l0, inv1 = 1.f / run_l1;

    const int r  = q0 + warp * 16 + (lane >> 2);
    const int cb = h * 64 + (lane & 3) * 2;
    #pragma unroll
    for (int vt = 0; vt < 8; ++vt) {
        float2 v0 = { o[vt][0] * inv0, o[vt][1] * inv0 };
        float2 v1 = { o[vt][2] * inv1, o[vt][3] * inv1 };
        *(float2*)(O + ((long)b*SEQ + r)     * DMODEL + cb + vt*8) = v0;
        *(float2*)(O + ((long)b*SEQ + r + 8) * DMODEL + cb + vt*8) = v1;
    }
}

// ------------------------- residual + LayerNorm (+ split planes) ----------
// Single fused reduction tree: (sum, sumsq) in one pass.
__global__ void ln_kernel(const float* __restrict__ X, const float* __restrict__ R,
                          const float* __restrict__ gamma, const float* __restrict__ beta,
                          float* __restrict__ Y,
                          bf16* __restrict__ Yh, bf16* __restrict__ Yl)
{
    const long row = blockIdx.x;
    const int tid = threadIdx.x;           // 128 threads, 4 elems each
    __shared__ float2 red[128];
    const int i = tid * 4;
    float4 a = *(const float4*)(X + row*DMODEL + i);
    float4 b = *(const float4*)(R + row*DMODEL + i);
    float z0 = a.x + b.x, z1 = a.y + b.y, z2 = a.z + b.z, z3 = a.w + b.w;

    // one tree reduces sum and sumsq together
    float s  = z0 + z1 + z2 + z3;
    float sq = z0*z0 + z1*z1 + z2*z2 + z3*z3;
    red[tid] = make_float2(s, sq); __syncthreads();
    for (int st = 64; st > 0; st >>= 1) {
        if (tid < st) {
            red[tid].x += red[tid+st].x;
            red[tid].y += red[tid+st].y;
        }
        __syncthreads();
    }
    const float mu = red[0].x * (1.f / DMODEL);
    // var*(n-1) = sumsq - n*mu^2  (algebraically identical to sum((z-mu)^2))
    const float ss = red[0].y - DMODEL * mu * mu;
    const float sigma = sqrtf(fmaxf(ss, 0.f) * (1.f / (DMODEL - 1)));
    const float sc = 1.f / (sigma + EPS);

    float d0 = z0-mu, d1 = z1-mu, d2 = z2-mu, d3 = z3-mu;
    float4 g4 = *(const float4*)(gamma + i);
    float4 be = *(const float4*)(beta + i);
    float4 y;
    y.x = d0 * sc * g4.x + be.x;
    y.y = d1 * sc * g4.y + be.y;
    y.z = d2 * sc * g4.z + be.z;
    y.w = d3 * sc * g4.w + be.w;
    *(float4*)(Y + row*DMODEL + i) = y;

    bf16 h0,l0,h1,l1,h2,l2,h3,l3;
    split1(y.x,h0,l0); split1(y.y,h1,l1); split1(y.z,h2,l2); split1(y.w,h3,l3);
    *(uint2*)(Yh + row*DMODEL + i) = make_uint2(pack_bf16(h0,h1), pack_bf16(h2,h3));
    *(uint2*)(Yl + row*DMODEL + i) = make_uint2(pack_bf16(l0,l1), pack_bf16(l2,l3));
}

// ------------------------- launch ------------------------------------------
extern "C" void kernel_launch(void* const* d_in, const int* in_sizes, int n_in,
                              void* d_out, int out_size)
{
    (void)in_sizes; (void)n_in; (void)out_size;
    const float* x    = (const float*)d_in[0];
    const float* pos  = (const float*)d_in[1];
    const float* wq   = (const float*)d_in[2];
    const float* wk   = (const float*)d_in[3];
    const float* wv   = (const float*)d_in[4];
    const float* ln1a = (const float*)d_in[5];
    const float* ln1b = (const float*)d_in[6];
    const float* w1   = (const float*)d_in[7];
    const float* b1   = (const float*)d_in[8];
    const float* w2   = (const float*)d_in[9];
    const float* b2   = (const float*)d_in[10];
    const float* ln2a = (const float*)d_in[11];
    const float* ln2b = (const float*)d_in[12];
    float* out = (float*)d_out;

    float *gx, *ga, *go;
    bf16 *xh, *xl, *hh, *hl, *wqkvh, *wqkvl, *w1h, *w1l, *w2h, *w2l, *qkvh, *qkvl;
    cudaGetSymbolAddress((void**)&gx, g_x);
    cudaGetSymbolAddress((void**)&ga, g_att);
    cudaGetSymbolAddress((void**)&go, g_o);
    cudaGetSymbolAddress((void**)&xh, g_xh);
    cudaGetSymbolAddress((void**)&xl, g_xl);
    cudaGetSymbolAddress((void**)&hh, g_hh);
    cudaGetSymbolAddress((void**)&hl, g_hl);
    cudaGetSymbolAddress((void**)&wqkvh, g_wqkvh);
    cudaGetSymbolAddress((void**)&wqkvl, g_wqkvl);
    cudaGetSymbolAddress((void**)&w1h, g_w1h);
    cudaGetSymbolAddress((void**)&w1l, g_w1l);
    cudaGetSymbolAddress((void**)&w2h, g_w2h);
    cudaGetSymbolAddress((void**)&w2l, g_w2l);
    cudaGetSymbolAddress((void**)&qkvh, g_qkv_h);
    cudaGetSymbolAddress((void**)&qkvl, g_qkv_l);

    static bool attr_set = false;
    if (!attr_set) {
        cudaFuncSetAttribute(fa2_kernel,
                             cudaFuncAttributeMaxDynamicSharedMemorySize, FA_SMEM);
        cudaFuncSetAttribute(mma_gemm_bf<8,false,false,true>,
                             cudaFuncAttributeMaxDynamicSharedMemorySize, GEMM_SMEM);
        cudaFuncSetAttribute(mma_gemm_bf<0,true,true,true>,
                             cudaFuncAttributeMaxDynamicSharedMemorySize, GEMM_SMEM);
        cudaFuncSetAttribute(mma_gemm_bf<0,false,true,false>,
                             cudaFuncAttributeMaxDynamicSharedMemorySize, GEMM_SMEM);
        attr_set = true;
    }

    // prep: positional add (+ split), weight transpose/split
    add_pos_kernel<<<NTOK*DMODEL/512, 512>>>(x, pos, gx, xh, xl);
    transpose3_kernel<<<dim3(DHEAD/32, DMODEL/32, 3*NLAYERS*NHEAD), dim3(32,8)>>>(
        wq, wk, wv, wqkvh, wqkvl);
    split_kernel<<<NLAYERS*DINNER*DMODEL/1024, 256>>>(w1, w1h, w1l, NLAYERS*DINNER*DMODEL);
    split_kernel<<<NLAYERS*DMODEL*DINNER/1024, 256>>>(w2, w2h, w2l, NLAYERS*DMODEL*DINNER);

    const long wqkv_mat   = (long)DHEAD * DMODEL;
    const long wqkv_layer = 3L * NHEAD * wqkv_mat;
    const long qkv_mat    = (long)NTOK * DHEAD;

    for (int i = 0; i < NLAYERS; ++i) {
        // fused QKV: 24 mats [4096,512]x[64,512]^T -> split planes
        // (z<8 = Q heads get pre-scaled by 1/temper in the epilogue)
        mma_gemm_bf<8,false,false,true><<<dim3(1, NTOK/128, 3*NHEAD), 256, GEMM_SMEM>>>(
            xh, xl, wqkvh + i*wqkv_layer, wqkvl + i*wqkv_layer,
            nullptr, nullptr, qkvh, qkvl,
            NTOK, DHEAD, DMODEL, wqkv_mat, qkv_mat);

        fa2_kernel<<<dim3(SEQ/64, BATCH, NHEAD), 128, FA_SMEM>>>(qkvh, qkvl, ga);

        ln_kernel<<<NTOK, 128>>>(ga, gx, ln1a + i*DMODEL, ln1b + i*DMODEL, gx, xh, xl);

        // FFN1: h = relu(x @ w1^T + b1) -> split planes
        mma_gemm_bf<0,true,true,true><<<dim3(DINNER/64, NTOK/128, 1), 256, GEMM_SMEM>>>(
            xh, xl, w1h + (long)i*DINNER*DMODEL, w1l + (long)i*DINNER*DMODEL,
            nullptr, b1 + i*DINNER, hh, hl,
            NTOK, DINNER, DMODEL, 0, 0);
        // FFN2: o = h @ w2^T + b2 -> fp32
        mma_gemm_bf<0,false,true,false><<<dim3(DMODEL/64, NTOK/128, 1), 256, GEMM_SMEM>>>(
            hh, hl, w2h + (long)i*DMODEL*DINNER, w2l + (long)i*DMODEL*DINNER,
            go, b2 + i*DMODEL, nullptr, nullptr,
            NTOK, DMODEL, DINNER, 0, 0);

        ln_kernel<<<NTOK, 128>>>(go, gx, ln2a + i*DMODEL, ln2b + i*DMODEL, gx, xh, xl);
    }

    cudaMemcpyAsync(out, gx, (size_t)NTOK*DMODEL*sizeof(float),
                    cudaMemcpyDeviceToDevice);
}

// round 16
// speedup vs baseline: 1.6096x; 1.0331x over previous
#include <cuda_runtime.h>
#include <cuda_bf16.h>
#include <math.h>
#include <stdint.h>

#define BATCH 4
#define SEQ 1024
#define DMODEL 512
#define NHEAD 8
#define DHEAD 64
#define DINNER 1024
#define NLAYERS 2
#define NTOK (BATCH*SEQ)          // 4096
#define EPS 1e-3f
#define INV_TEMPER 0.044194173824159216f   // 1/sqrt(512)

typedef __nv_bfloat16 bf16;

// ------------------------- scratch (device globals; no runtime alloc) -----
__device__ float g_x  [NTOK*DMODEL];       // fp32 activations (residual path)
__device__ float g_att[NTOK*DMODEL];
__device__ float g_o  [NTOK*DMODEL];
__device__ bf16 g_xh[NTOK*DMODEL],  g_xl[NTOK*DMODEL];
__device__ bf16 g_hh[NTOK*DINNER],  g_hl[NTOK*DINNER];
__device__ bf16 g_wqkvh[NLAYERS*3*NHEAD*DHEAD*DMODEL];
__device__ bf16 g_wqkvl[NLAYERS*3*NHEAD*DHEAD*DMODEL];
__device__ bf16 g_w1h[NLAYERS*DINNER*DMODEL], g_w1l[NLAYERS*DINNER*DMODEL];
__device__ bf16 g_w2h[NLAYERS*DMODEL*DINNER], g_w2l[NLAYERS*DMODEL*DINNER];
__device__ bf16 g_qkv_h[3*NHEAD*NTOK*DHEAD];
__device__ bf16 g_qkv_l[3*NHEAD*NTOK*DHEAD];

// ------------------------- small helpers ----------------------------------
__device__ __forceinline__ uint32_t pack_bf16(bf16 a, bf16 b)
{
    __nv_bfloat162 t = __halves2bfloat162(a, b);
    return *(uint32_t*)&t;
}
__device__ __forceinline__ void split1(float v, bf16& h, bf16& l)
{
    h = __float2bfloat16(v);
    l = __float2bfloat16(v - __bfloat162float(h));
}

// ------------------------- x + pos_enc (fp32 + planes) --------------------
__global__ void add_pos_kernel(const float* __restrict__ x,
                               const float* __restrict__ pos,
                               float* __restrict__ y,
                               bf16* __restrict__ yh, bf16* __restrict__ yl)
{
    int idx = blockIdx.x * 512 + threadIdx.x;
    float v = x[idx] + pos[idx & (SEQ*DMODEL - 1)];
    y[idx] = v;
    bf16 h, l; split1(v, h, l);
    yh[idx] = h; yl[idx] = l;
}

// ------------------------- qkv weight transpose + split -------------------
__global__ void transpose3_kernel(const float* __restrict__ wq,
                                  const float* __restrict__ wk,
                                  const float* __restrict__ wv,
                                  bf16* __restrict__ oh, bf16* __restrict__ ol)
{
    __shared__ float tile[32][33];
    const int z = blockIdx.z;
    const int w = z / (NLAYERS*NHEAD);
    const int l = (z / NHEAD) % NLAYERS;
    const int h = z % NHEAD;
    const float* ip = (w == 0 ? wq : w == 1 ? wk : wv)
                      + (long)(l*NHEAD + h) * DMODEL * DHEAD;
    const long ob = (long)((l*3 + w)*NHEAD + h) * DHEAD * DMODEL;
    int c0 = blockIdx.x * 32, r0 = blockIdx.y * 32;
    for (int i = threadIdx.y; i < 32; i += 8)
        tile[i][threadIdx.x] = ip[(long)(r0 + i) * DHEAD + c0 + threadIdx.x];
    __syncthreads();
    for (int i = threadIdx.y; i < 32; i += 8) {
        float v = tile[threadIdx.x][i];
        bf16 hh, ll; split1(v, hh, ll);
        long o = ob + (long)(c0 + i) * DMODEL + r0 + threadIdx.x;
        oh[o] = hh; ol[o] = ll;
    }
}

// ------------------------- generic fp32 -> split planes -------------------
__global__ void split_kernel(const float* __restrict__ in,
                             bf16* __restrict__ oh, bf16* __restrict__ ol, int n)
{
    int idx = (blockIdx.x * 256 + threadIdx.x) * 4;
    if (idx >= n) return;
    float4 v = *(const float4*)(in + idx);
    bf16 h0,l0,h1,l1,h2,l2,h3,l3;
    split1(v.x,h0,l0); split1(v.y,h1,l1); split1(v.z,h2,l2); split1(v.w,h3,l3);
    *(uint2*)(oh + idx) = make_uint2(pack_bf16(h0,h1), pack_bf16(h2,h3));
    *(uint2*)(ol + idx) = make_uint2(pack_bf16(l0,l1), pack_bf16(l2,l3));
}

// ------------------------- mma / ldsm / cp.async helpers ------------------
__device__ __forceinline__ void ldsm4(uint32_t* r, uint32_t addr)
{
    asm volatile("ldmatrix.sync.aligned.m8n8.x4.shared.b16 {%0,%1,%2,%3}, [%4];"
        : "=r"(r[0]), "=r"(r[1]), "=r"(r[2]), "=r"(r[3]) : "r"(addr));
}
__device__ __forceinline__ void ldsm4t(uint32_t* r, uint32_t addr)
{
    asm volatile("ldmatrix.sync.aligned.m8n8.x4.trans.shared.b16 {%0,%1,%2,%3}, [%4];"
        : "=r"(r[0]), "=r"(r[1]), "=r"(r[2]), "=r"(r[3]) : "r"(addr));
}
__device__ __forceinline__ void mma_bf16(float* c, const uint32_t* a,
                                         uint32_t b0, uint32_t b1)
{
    asm volatile(
        "mma.sync.aligned.m16n8k16.row.col.f32.bf16.bf16.f32 "
        "{%0,%1,%2,%3}, {%4,%5,%6,%7}, {%8,%9}, {%0,%1,%2,%3};\n"
        : "+f"(c[0]), "+f"(c[1]), "+f"(c[2]), "+f"(c[3])
        : "r"(a[0]), "r"(a[1]), "r"(a[2]), "r"(a[3]), "r"(b0), "r"(b1));
}
__device__ __forceinline__ void packsplit(float x, float y, uint32_t& hi, uint32_t& lo)
{
    bf16 hx = __float2bfloat16(x), hy = __float2bfloat16(y);
    hi = pack_bf16(hx, hy);
    lo = pack_bf16(__float2bfloat16(x - __bfloat162float(hx)),
                   __float2bfloat16(y - __bfloat162float(hy)));
}
__device__ __forceinline__ void cpa16(uint32_t dst, const void* src)
{
    asm volatile("cp.async.cg.shared.global [%0], [%1], 16;\n" :: "r"(dst), "l"(src));
}
__device__ __forceinline__ void cpa_commit()
{
    asm volatile("cp.async.commit_group;\n");
}
template<int N> __device__ __forceinline__ void cpa_wait()
{
    asm volatile("cp.async.wait_group %0;\n" :: "n"(N));
}
// GEMM smem swizzle: 64B rows (32 bf16), 4x16B chunks
__device__ __forceinline__ int swoff(int row, int chunk)
{
    return row * 64 + ((chunk ^ ((row >> 1) & 3)) * 16);
}
// attention plane swizzle: 128B rows (64 bf16), 8x16B chunks
__device__ __forceinline__ uint32_t swz128(int row, int c16)
{
    return (uint32_t)(row * 128 + ((c16 ^ (row & 7)) * 16));
}

// ------------------------- split-bf16 tensor-core GEMM (NT) ----------------
// C = A * B^T; A,B given as hi/lo bf16 planes (row-major, K contiguous).
// BM=128, BN=64, BK=32, 256 thr, 3-stage cp.async pipeline.
// ALO: include the A-lo correction term (Al*Bh). When false the GEMM runs
// 2 terms (Ah*Bh + Ah*Bl) and skips loading the Al plane entirely.
// QSCALEZ: blocks with blockIdx.z < QSCALEZ scale output by 1/temper.
#define GEMM_SMEM 73728

template<int QSCALEZ, bool RELU, bool HASBIAS, bool SPLIT, bool ALO>
__global__ __launch_bounds__(256, 2)
void mma_gemm_bf(const bf16* __restrict__ Ah, const bf16* __restrict__ Al,
                 const bf16* __restrict__ Bh, const bf16* __restrict__ Bl,
                 float* __restrict__ C, const float* __restrict__ bias,
                 bf16* __restrict__ Chi, bf16* __restrict__ Clo,
                 int M, int N, int K, long strideB, long strideC)
{
    extern __shared__ uint8_t sm[];
    Bh += (long)blockIdx.z * strideB;
    Bl += (long)blockIdx.z * strideB;
    if (SPLIT) { Chi += (long)blockIdx.z * strideC; Clo += (long)blockIdx.z * strideC; }
    else       { C   += (long)blockIdx.z * strideC; }
    const int bm = blockIdx.y * 128, bn = blockIdx.x * 64;
    const int tid = threadIdx.x, lane = tid & 31, warp = tid >> 5;
    const int wm = (warp & 1) * 64, wn = (warp >> 1) * 16;
    const uint32_t sbase = (uint32_t)__cvta_generic_to_shared(sm);

    const int arow = tid >> 1, acb = (tid & 1) * 2;
    const int brow = tid >> 2, bcb = tid & 3;
    const long aoff = (long)(bm + arow) * K;
    const long boff = (long)(bn + brow) * K;
    const uint32_t ad0 = swoff(arow, acb), ad1 = swoff(arow, acb + 1);
    const uint32_t bd0 = swoff(brow, bcb);

    auto issue = [&](int slot, int k0) {
        const uint32_t s = sbase + slot * 24576;
        cpa16(s + ad0,         Ah + aoff + k0 + acb*8);
        cpa16(s + ad1,         Ah + aoff + k0 + acb*8 + 8);
        if (ALO) {
            cpa16(s + 8192 + ad0,  Al + aoff + k0 + acb*8);
            cpa16(s + 8192 + ad1,  Al + aoff + k0 + acb*8 + 8);
        }
        cpa16(s + 16384 + bd0, Bh + boff + k0 + bcb*8);
        cpa16(s + 20480 + bd0, Bl + boff + k0 + bcb*8);
    };

    float acc[4][2][4];
    #pragma unroll
    for (int mt = 0; mt < 4; ++mt)
        #pragma unroll
        for (int n2 = 0; n2 < 2; ++n2)
            #pragma unroll
            for (int j = 0; j < 4; ++j) acc[mt][n2][j] = 0.f;

    issue(0, 0);  cpa_commit();
    issue(1, 32); cpa_commit();

    const int nt = K / 32;
    #pragma unroll 1
    for (int t = 0; t < nt; ++t) {
        cpa_wait<1>();
        __syncthreads();
        const uint32_t aH = sbase + (t % 3) * 24576;
        const uint32_t aL = aH + 8192;
        const uint32_t bH = aH + 16384;
        const uint32_t bL = aH + 20480;
        #pragma unroll
        for (int kk = 0; kk < 2; ++kk) {
            const int kc = kk * 2 + (lane >> 4);
            const int br = wn + (lane & 15);
            uint32_t bhf[4], blf[4];
            ldsm4(bhf, bH + swoff(br, kc));
            ldsm4(blf, bL + swoff(br, kc));
            #pragma unroll
            for (int mt = 0; mt < 4; ++mt) {
                const int ar = wm + mt * 16 + (lane & 15);
                uint32_t ahf[4];
                ldsm4(ahf, aH + swoff(ar, kc));
                #pragma unroll
                for (int n2 = 0; n2 < 2; ++n2) {
                    mma_bf16(acc[mt][n2], ahf, bhf[n2], bhf[n2 + 2]);
                    mma_bf16(acc[mt][n2], ahf, blf[n2], blf[n2 + 2]);
                }
                if (ALO) {
                    uint32_t alf[4];
                    ldsm4(alf, aL + swoff(ar, kc));
                    #pragma unroll
                    for (int n2 = 0; n2 < 2; ++n2)
                        mma_bf16(acc[mt][n2], alf, bhf[n2], bhf[n2 + 2]);
                }
            }
        }
        if (t + 2 < nt) issue((t + 2) % 3, (t + 2) * 32);
        cpa_commit();
    }

    const bool qscale = (QSCALEZ > 0) && ((int)blockIdx.z < QSCALEZ);
    #pragma unroll
    for (int mt = 0; mt < 4; ++mt) {
        const int r0 = bm + wm + mt * 16 + (lane >> 2);
        #pragma unroll
        for (int n2 = 0; n2 < 2; ++n2) {
            const int col = bn + wn + n2 * 8 + (lane & 3) * 2;
            float2 v0 = { acc[mt][n2][0], acc[mt][n2][1] };
            float2 v1 = { acc[mt][n2][2], acc[mt][n2][3] };
            if (HASBIAS) {
                float b0 = bias[col], b1 = bias[col + 1];
                v0.x += b0; v0.y += b1; v1.x += b0; v1.y += b1;
            }
            if (RELU) {
                v0.x = fmaxf(v0.x, 0.f); v0.y = fmaxf(v0.y, 0.f);
                v1.x = fmaxf(v1.x, 0.f); v1.y = fmaxf(v1.y, 0.f);
            }
            if (QSCALEZ > 0 && qscale) {
                v0.x *= INV_TEMPER; v0.y *= INV_TEMPER;
                v1.x *= INV_TEMPER; v1.y *= INV_TEMPER;
            }
            if (SPLIT) {
                bf16 h0, l0, h1, l1, h2, l2, h3, l3;
                split1(v0.x, h0, l0); split1(v0.y, h1, l1);
                split1(v1.x, h2, l2); split1(v1.y, h3, l3);
                *(uint32_t*)(Chi + (long)r0 * N + col)       = pack_bf16(h0, h1);
                *(uint32_t*)(Chi + (long)(r0 + 8) * N + col) = pack_bf16(h2, h3);
                *(uint32_t*)(Clo + (long)r0 * N + col)       = pack_bf16(l0, l1);
                *(uint32_t*)(Clo + (long)(r0 + 8) * N + col) = pack_bf16(l2, l3);
            } else {
                *(float2*)(C + (long)r0 * N + col) = v0;
                *(float2*)(C + (long)(r0 + 8) * N + col) = v1;
            }
        }
    }
}

// ------------------------- FA2 tensor-core attention ----------------------
// R14 winner: 64-row q tile, 128 thr, occ 2. QK = 3 terms, PV = 2 terms.
#define FA_SMEM 81920
#define FA_STAGE 32768
#define ST_KH 0
#define ST_KL 8192
#define ST_VH 16384
#define ST_VL 24576
#define FA_QH 65536
#define FA_QL 73728

__global__ __launch_bounds__(128, 2)
void fa2_kernel(const bf16* __restrict__ QKVh,
                const bf16* __restrict__ QKVl,
                float* __restrict__ O)
{
    extern __shared__ uint8_t sm[];
    const uint32_t sbase = (uint32_t)__cvta_generic_to_shared(sm);

    const int h = blockIdx.z, b = blockIdx.y;
    const int q0 = blockIdx.x * 64;
    const int tid = threadIdx.x, lane = tid & 31, warp = tid >> 5;

    const long planeQ = ((long)h * NTOK + (long)b * SEQ) * DHEAD;
    const long planeK = ((long)(NHEAD + h) * NTOK + (long)b * SEQ) * DHEAD;
    const long planeV = ((long)(2*NHEAD + h) * NTOK + (long)b * SEQ) * DHEAD;

    int crow[4], cc16[4];
    #pragma unroll
    for (int p = 0; p < 4; ++p) {
        int ci = tid + p * 128;
        crow[p] = ci >> 3; cc16[p] = ci & 7;
    }

    #pragma unroll
    for (int p = 0; p < 4; ++p) {
        const uint32_t so = swz128(crow[p], cc16[p]);
        const long ro = (long)(q0 + crow[p]) * 64 + cc16[p] * 8;
        cpa16(sbase + FA_QH + so, QKVh + planeQ + ro);
        cpa16(sbase + FA_QL + so, QKVl + planeQ + ro);
    }
    cpa_commit();
    #pragma unroll
    for (int p = 0; p < 4; ++p) {
        const long ro = (long)crow[p] * 64 + cc16[p] * 8;
        const uint32_t so = swz128(crow[p], cc16[p]);
        cpa16(sbase + ST_KH + so, QKVh + planeK + ro);
        cpa16(sbase + ST_KL + so, QKVl + planeK + ro);
        cpa16(sbase + ST_VH + so, QKVh + planeV + ro);
        cpa16(sbase + ST_VL + so, QKVl + planeV + ro);
    }
    cpa_commit();

    cpa_wait<1>();
    __syncthreads();

    uint32_t qh[4][4], ql[4][4];
    {
        const int qrow = warp * 16 + (lane & 15);
        #pragma unroll
        for (int ks = 0; ks < 4; ++ks) {
            ldsm4(qh[ks], sbase + FA_QH + swz128(qrow, 2*ks + (lane >> 4)));
            ldsm4(ql[ks], sbase + FA_QL + swz128(qrow, 2*ks + (lane >> 4)));
        }
    }

    float o[8][4];
    #pragma unroll
    for (int vt = 0; vt < 8; ++vt)
        #pragma unroll
        for (int j = 0; j < 4; ++j) o[vt][j] = 0.f;
    float run_m0 = -INFINITY, run_m1 = -INFINITY;
    float run_l0 = 0.f, run_l1 = 0.f;

    #pragma unroll 1
    for (int c = 0; c < 16; ++c) {
        const uint32_t stg = sbase + (c & 1) * FA_STAGE;
        if (c < 15) {
            const uint32_t nst = sbase + ((c + 1) & 1) * FA_STAGE;
            const long m0 = (long)(c + 1) * 64;
            #pragma unroll
            for (int p = 0; p < 4; ++p) {
                const long ro = (m0 + crow[p]) * 64 + cc16[p] * 8;
                const uint32_t so = swz128(crow[p], cc16[p]);
                cpa16(nst + ST_KH + so, QKVh + planeK + ro);
                cpa16(nst + ST_KL + so, QKVl + planeK + ro);
                cpa16(nst + ST_VH + so, QKVh + planeV + ro);
                cpa16(nst + ST_VL + so, QKVl + planeV + ro);
            }
            cpa_commit();
            cpa_wait<1>();
        } else {
            cpa_wait<0>();
        }
        __syncthreads();

        // ---- S = Q K^T (split bf16, 3 terms), 8 n8-tiles (64 K rows)
        float s[8][4];
        #pragma unroll
        for (int t = 0; t < 8; ++t)
            #pragma unroll
            for (int j = 0; j < 4; ++j) s[t][j] = 0.f;
        #pragma unroll
        for (int g = 0; g < 4; ++g) {
            const int krow = g * 16 + (lane & 15);
            #pragma unroll
            for (int ks = 0; ks < 4; ++ks) {
                const uint32_t so = swz128(krow, 2*ks + (lane >> 4));
                uint32_t khf[4], klf[4];
                ldsm4(khf, stg + ST_KH + so);
                ldsm4(klf, stg + ST_KL + so);
                #pragma unroll
                for (int n2 = 0; n2 < 2; ++n2) {
                    float* st = s[g*2 + n2];
                    mma_bf16(st, qh[ks], khf[n2], khf[n2 + 2]);
                    mma_bf16(st, qh[ks], klf[n2], klf[n2 + 2]);
                    mma_bf16(st, ql[ks], khf[n2], khf[n2 + 2]);
                }
            }
        }

        // ---- online softmax (rows r = lane>>2, r+8); scores pre-scaled
        float mx0 = -INFINITY, mx1 = -INFINITY;
        #pragma unroll
        for (int t = 0; t < 8; ++t) {
            mx0 = fmaxf(mx0, fmaxf(s[t][0], s[t][1]));
            mx1 = fmaxf(mx1, fmaxf(s[t][2], s[t][3]));
        }
        mx0 = fmaxf(mx0, __shfl_xor_sync(0xffffffffu, mx0, 1));
        mx0 = fmaxf(mx0, __shfl_xor_sync(0xffffffffu, mx0, 2));
        mx1 = fmaxf(mx1, __shfl_xor_sync(0xffffffffu, mx1, 1));
        mx1 = fmaxf(mx1, __shfl_xor_sync(0xffffffffu, mx1, 2));

        const float nm0 = fmaxf(run_m0, mx0);
        const float nm1 = fmaxf(run_m1, mx1);
        const float sc0 = __expf(run_m0 - nm0);
        const float sc1 = __expf(run_m1 - nm1);
        run_m0 = nm0; run_m1 = nm1;

        float ps0 = 0.f, ps1 = 0.f;
        #pragma unroll
        for (int t = 0; t < 8; ++t) {
            float p0 = __expf(s[t][0] - nm0); s[t][0] = p0;
            float p1 = __expf(s[t][1] - nm0); s[t][1] = p1;
            float p2 = __expf(s[t][2] - nm1); s[t][2] = p2;
            float p3 = __expf(s[t][3] - nm1); s[t][3] = p3;
            ps0 += p0 + p1; ps1 += p2 + p3;
        }
        run_l0 = run_l0 * sc0 + ps0;
        run_l1 = run_l1 * sc1 + ps1;
        #pragma unroll
        for (int vt = 0; vt < 8; ++vt) {
            o[vt][0] *= sc0; o[vt][1] *= sc0;
            o[vt][2] *= sc1; o[vt][3] *= sc1;
        }

        // ---- O += P V : 2 terms (Ph*Vh + Ph*Vl)
        #pragma unroll
        for (int ks = 0; ks < 4; ++ks) {
            uint32_t ah[4];
            ah[0] = pack_bf16(__float2bfloat16(s[2*ks][0]),   __float2bfloat16(s[2*ks][1]));
            ah[1] = pack_bf16(__float2bfloat16(s[2*ks][2]),   __float2bfloat16(s[2*ks][3]));
            ah[2] = pack_bf16(__float2bfloat16(s[2*ks+1][0]), __float2bfloat16(s[2*ks+1][1]));
            ah[3] = pack_bf16(__float2bfloat16(s[2*ks+1][2]), __float2bfloat16(s[2*ks+1][3]));
            const int vrow = ks * 16 + (lane & 15);
            #pragma unroll
            for (int vg = 0; vg < 4; ++vg) {
                const uint32_t so = swz128(vrow, vg*2 + (lane >> 4));
                uint32_t vhf[4], vlf[4];
                ldsm4t(vhf, stg + ST_VH + so);
                ldsm4t(vlf, stg + ST_VL + so);
                #pragma unroll
                for (int n2 = 0; n2 < 2; ++n2) {
                    float* ot = o[vg*2 + n2];
                    mma_bf16(ot, ah, vhf[2*n2], vhf[2*n2 + 1]);
                    mma_bf16(ot, ah, vlf[2*n2], vlf[2*n2 + 1]);
                }
            }
        }
        __syncthreads();
    }

    run_l0 += __shfl_xor_sync(0xffffffffu, run_l0, 1);
    run_l0 += __shfl_xor_sync(0xffffffffu, run_l0, 2);
    run_l1 += __shfl_xor_sync(0xffffffffu, run_l1, 1);
    run_l1 += __shfl_xor_sync(0xffffffffu, run_l1, 2);
    const float inv0 = 1.f / run_l0, inv1 = 1.f / run_l1;

    const int r  = q0 + warp * 16 + (lane >> 2);
    const int cb = h * 64 + (lane & 3) * 2;
    #pragma unroll
    for (int vt = 0; vt < 8; ++vt) {
        float2 v0 = { o[vt][0] * inv0, o[vt][1] * inv0 };
        float2 v1 = { o[vt][2] * inv1, o[vt][3] * inv1 };
        *(float2*)(O + ((long)b*SEQ + r)     * DMODEL + cb + vt*8) = v0;
        *(float2*)(O + ((long)b*SEQ + r + 8) * DMODEL + cb + vt*8) = v1;
    }
}

// ------------------------- residual + LayerNorm (+ split planes) ----------
// Single fused reduction tree: (sum, sumsq) in one pass.
__global__ void ln_kernel(const float* __restrict__ X, const float* __restrict__ R,
                          const float* __restrict__ gamma, const float* __restrict__ beta,
                          float* __restrict__ Y,
                          bf16* __restrict__ Yh, bf16* __restrict__ Yl)
{
    const long row = blockIdx.x;
    const int tid = threadIdx.x;           // 128 threads, 4 elems each
    __shared__ float2 red[128];
    const int i = tid * 4;
    float4 a = *(const float4*)(X + row*DMODEL + i);
    float4 b = *(const float4*)(R + row*DMODEL + i);
    float z0 = a.x + b.x, z1 = a.y + b.y, z2 = a.z + b.z, z3 = a.w + b.w;

    float s  = z0 + z1 + z2 + z3;
    float sq = z0*z0 + z1*z1 + z2*z2 + z3*z3;
    red[tid] = make_float2(s, sq); __syncthreads();
    for (int st = 64; st > 0; st >>= 1) {
        if (tid < st) {
            red[tid].x += red[tid+st].x;
            red[tid].y += red[tid+st].y;
        }
        __syncthreads();
    }
    const float mu = red[0].x * (1.f / DMODEL);
    const float ss = red[0].y - DMODEL * mu * mu;
    const float sigma = sqrtf(fmaxf(ss, 0.f) * (1.f / (DMODEL - 1)));
    const float sc = 1.f / (sigma + EPS);

    float d0 = z0-mu, d1 = z1-mu, d2 = z2-mu, d3 = z3-mu;
    float4 g4 = *(const float4*)(gamma + i);
    float4 be = *(const float4*)(beta + i);
    float4 y;
    y.x = d0 * sc * g4.x + be.x;
    y.y = d1 * sc * g4.y + be.y;
    y.z = d2 * sc * g4.z + be.z;
    y.w = d3 * sc * g4.w + be.w;
    *(float4*)(Y + row*DMODEL + i) = y;

    bf16 h0,l0,h1,l1,h2,l2,h3,l3;
    split1(y.x,h0,l0); split1(y.y,h1,l1); split1(y.z,h2,l2); split1(y.w,h3,l3);
    *(uint2*)(Yh + row*DMODEL + i) = make_uint2(pack_bf16(h0,h1), pack_bf16(h2,h3));
    *(uint2*)(Yl + row*DMODEL + i) = make_uint2(pack_bf16(l0,l1), pack_bf16(l2,l3));
}

// ------------------------- launch ------------------------------------------
extern "C" void kernel_launch(void* const* d_in, const int* in_sizes, int n_in,
                              void* d_out, int out_size)
{
    (void)in_sizes; (void)n_in; (void)out_size;
    const float* x    = (const float*)d_in[0];
    const float* pos  = (const float*)d_in[1];
    const float* wq   = (const float*)d_in[2];
    const float* wk   = (const float*)d_in[3];
    const float* wv   = (const float*)d_in[4];
    const float* ln1a = (const float*)d_in[5];
    const float* ln1b = (const float*)d_in[6];
    const float* w1   = (const float*)d_in[7];
    const float* b1   = (const float*)d_in[8];
    const float* w2   = (const float*)d_in[9];
    const float* b2   = (const float*)d_in[10];
    const float* ln2a = (const float*)d_in[11];
    const float* ln2b = (const float*)d_in[12];
    float* out = (float*)d_out;

    float *gx, *ga, *go;
    bf16 *xh, *xl, *hh, *hl, *wqkvh, *wqkvl, *w1h, *w1l, *w2h, *w2l, *qkvh, *qkvl;
    cudaGetSymbolAddress((void**)&gx, g_x);
    cudaGetSymbolAddress((void**)&ga, g_att);
    cudaGetSymbolAddress((void**)&go, g_o);
    cudaGetSymbolAddress((void**)&xh, g_xh);
    cudaGetSymbolAddress((void**)&xl, g_xl);
    cudaGetSymbolAddress((void**)&hh, g_hh);
    cudaGetSymbolAddress((void**)&hl, g_hl);
    cudaGetSymbolAddress((void**)&wqkvh, g_wqkvh);
    cudaGetSymbolAddress((void**)&wqkvl, g_wqkvl);
    cudaGetSymbolAddress((void**)&w1h, g_w1h);
    cudaGetSymbolAddress((void**)&w1l, g_w1l);
    cudaGetSymbolAddress((void**)&w2h, g_w2h);
    cudaGetSymbolAddress((void**)&w2l, g_w2l);
    cudaGetSymbolAddress((void**)&qkvh, g_qkv_h);
    cudaGetSymbolAddress((void**)&qkvl, g_qkv_l);

    static bool attr_set = false;
    if (!attr_set) {
        cudaFuncSetAttribute(fa2_kernel,
                             cudaFuncAttributeMaxDynamicSharedMemorySize, FA_SMEM);
        cudaFuncSetAttribute(mma_gemm_bf<8,false,false,true,true>,
                             cudaFuncAttributeMaxDynamicSharedMemorySize, GEMM_SMEM);
        cudaFuncSetAttribute(mma_gemm_bf<0,true,true,true,false>,
                             cudaFuncAttributeMaxDynamicSharedMemorySize, GEMM_SMEM);
        cudaFuncSetAttribute(mma_gemm_bf<0,false,true,false,true>,
                             cudaFuncAttributeMaxDynamicSharedMemorySize, GEMM_SMEM);
        attr_set = true;
    }

    // prep: positional add (+ split), weight transpose/split
    add_pos_kernel<<<NTOK*DMODEL/512, 512>>>(x, pos, gx, xh, xl);
    transpose3_kernel<<<dim3(DHEAD/32, DMODEL/32, 3*NLAYERS*NHEAD), dim3(32,8)>>>(
        wq, wk, wv, wqkvh, wqkvl);
    split_kernel<<<NLAYERS*DINNER*DMODEL/1024, 256>>>(w1, w1h, w1l, NLAYERS*DINNER*DMODEL);
    split_kernel<<<NLAYERS*DMODEL*DINNER/1024, 256>>>(w2, w2h, w2l, NLAYERS*DMODEL*DINNER);

    const long wqkv_mat   = (long)DHEAD * DMODEL;
    const long wqkv_layer = 3L * NHEAD * wqkv_mat;
    const long qkv_mat    = (long)NTOK * DHEAD;

    for (int i = 0; i < NLAYERS; ++i) {
        // fused QKV: 24 mats [4096,512]x[64,512]^T -> split planes, 3 terms
        // (z<8 = Q heads get pre-scaled by 1/temper in the epilogue)
        mma_gemm_bf<8,false,false,true,true><<<dim3(1, NTOK/128, 3*NHEAD), 256, GEMM_SMEM>>>(
            xh, xl, wqkvh + i*wqkv_layer, wqkvl + i*wqkv_layer,
            nullptr, nullptr, qkvh, qkvl,
            NTOK, DHEAD, DMODEL, wqkv_mat, qkv_mat);

        fa2_kernel<<<dim3(SEQ/64, BATCH, NHEAD), 128, FA_SMEM>>>(qkvh, qkvl, ga);

        ln_kernel<<<NTOK, 128>>>(ga, gx, ln1a + i*DMODEL, ln1b + i*DMODEL, gx, xh, xl);

        // FFN1: h = relu(x @ w1^T + b1) -> split planes; 2 terms (A-lo dropped:
        // x is post-LN ~N(0,1); error smoothed through FFN2's 1024-wide sum)
        mma_gemm_bf<0,true,true,true,false><<<dim3(DINNER/64, NTOK/128, 1), 256, GEMM_SMEM>>>(
            xh, xl, w1h + (long)i*DINNER*DMODEL, w1l + (long)i*DINNER*DMODEL,
            nullptr, b1 + i*DINNER, hh, hl,
            NTOK, DINNER, DMODEL, 0, 0);
        // FFN2: o = h @ w2^T + b2 -> fp32, 3 terms
        mma_gemm_bf<0,false,true,false,true><<<dim3(DMODEL/64, NTOK/128, 1), 256, GEMM_SMEM>>>(
            hh, hl, w2h + (long)i*DMODEL*DINNER, w2l + (long)i*DMODEL*DINNER,
            go, b2 + i*DMODEL, nullptr, nullptr,
            NTOK, DMODEL, DINNER, 0, 0);

        ln_kernel<<<NTOK, 128>>>(go, gx, ln2a + i*DMODEL, ln2b + i*DMODEL, gx, xh, xl);
    }

    cudaMemcpyAsync(out, gx, (size_t)NTOK*DMODEL*sizeof(float),
                    cudaMemcpyDeviceToDevice);
}

// round 17
// speedup vs baseline: 1.7854x; 1.1093x over previous
#include <cuda_runtime.h>
#include <cuda_bf16.h>
#include <math.h>
#include <stdint.h>

#define BATCH 4
#define SEQ 1024
#define DMODEL 512
#define NHEAD 8
#define DHEAD 64
#define DINNER 1024
#define NLAYERS 2
#define NTOK (BATCH*SEQ)          // 4096
#define EPS 1e-3f
#define INV_TEMPER 0.044194173824159216f   // 1/sqrt(512)

typedef __nv_bfloat16 bf16;

// ------------------------- scratch (device globals; no runtime alloc) -----
__device__ float g_x  [NTOK*DMODEL];       // fp32 activations (residual path)
__device__ float g_att[NTOK*DMODEL];
__device__ float g_o  [NTOK*DMODEL];
__device__ bf16 g_xh[NTOK*DMODEL],  g_xl[NTOK*DMODEL];
__device__ bf16 g_hh[NTOK*DINNER];
__device__ bf16 g_wqkvh[NLAYERS*3*NHEAD*DHEAD*DMODEL];
__device__ bf16 g_wqkvl[NLAYERS*3*NHEAD*DHEAD*DMODEL];
__device__ bf16 g_w1h[NLAYERS*DINNER*DMODEL], g_w1l[NLAYERS*DINNER*DMODEL];
__device__ bf16 g_w2h[NLAYERS*DMODEL*DINNER], g_w2l[NLAYERS*DMODEL*DINNER];
__device__ bf16 g_qkv_h[3*NHEAD*NTOK*DHEAD];
__device__ bf16 g_qkv_l[3*NHEAD*NTOK*DHEAD];

// ------------------------- small helpers ----------------------------------
__device__ __forceinline__ uint32_t pack_bf16(bf16 a, bf16 b)
{
    __nv_bfloat162 t = __halves2bfloat162(a, b);
    return *(uint32_t*)&t;
}
__device__ __forceinline__ void split1(float v, bf16& h, bf16& l)
{
    h = __float2bfloat16(v);
    l = __float2bfloat16(v - __bfloat162float(h));
}

// ------------------------- x + pos_enc (fp32 + planes) --------------------
__global__ void add_pos_kernel(const float* __restrict__ x,
                               const float* __restrict__ pos,
                               float* __restrict__ y,
                               bf16* __restrict__ yh, bf16* __restrict__ yl)
{
    int idx = blockIdx.x * 512 + threadIdx.x;
    float v = x[idx] + pos[idx & (SEQ*DMODEL - 1)];
    y[idx] = v;
    bf16 h, l; split1(v, h, l);
    yh[idx] = h; yl[idx] = l;
}

// ------------------------- qkv weight transpose + split -------------------
__global__ void transpose3_kernel(const float* __restrict__ wq,
                                  const float* __restrict__ wk,
                                  const float* __restrict__ wv,
                                  bf16* __restrict__ oh, bf16* __restrict__ ol)
{
    __shared__ float tile[32][33];
    const int z = blockIdx.z;
    const int w = z / (NLAYERS*NHEAD);
    const int l = (z / NHEAD) % NLAYERS;
    const int h = z % NHEAD;
    const float* ip = (w == 0 ? wq : w == 1 ? wk : wv)
                      + (long)(l*NHEAD + h) * DMODEL * DHEAD;
    const long ob = (long)((l*3 + w)*NHEAD + h) * DHEAD * DMODEL;
    int c0 = blockIdx.x * 32, r0 = blockIdx.y * 32;
    for (int i = threadIdx.y; i < 32; i += 8)
        tile[i][threadIdx.x] = ip[(long)(r0 + i) * DHEAD + c0 + threadIdx.x];
    __syncthreads();
    for (int i = threadIdx.y; i < 32; i += 8) {
        float v = tile[threadIdx.x][i];
        bf16 hh, ll; split1(v, hh, ll);
        long o = ob + (long)(c0 + i) * DMODEL + r0 + threadIdx.x;
        oh[o] = hh; ol[o] = ll;
    }
}

// ------------------------- generic fp32 -> split planes -------------------
__global__ void split_kernel(const float* __restrict__ in,
                             bf16* __restrict__ oh, bf16* __restrict__ ol, int n)
{
    int idx = (blockIdx.x * 256 + threadIdx.x) * 4;
    if (idx >= n) return;
    float4 v = *(const float4*)(in + idx);
    bf16 h0,l0,h1,l1,h2,l2,h3,l3;
    split1(v.x,h0,l0); split1(v.y,h1,l1); split1(v.z,h2,l2); split1(v.w,h3,l3);
    *(uint2*)(oh + idx) = make_uint2(pack_bf16(h0,h1), pack_bf16(h2,h3));
    *(uint2*)(ol + idx) = make_uint2(pack_bf16(l0,l1), pack_bf16(l2,l3));
}

// ------------------------- mma / ldsm / cp.async helpers ------------------
__device__ __forceinline__ void ldsm4(uint32_t* r, uint32_t addr)
{
    asm volatile("ldmatrix.sync.aligned.m8n8.x4.shared.b16 {%0,%1,%2,%3}, [%4];"
        : "=r"(r[0]), "=r"(r[1]), "=r"(r[2]), "=r"(r[3]) : "r"(addr));
}
__device__ __forceinline__ void ldsm4t(uint32_t* r, uint32_t addr)
{
    asm volatile("ldmatrix.sync.aligned.m8n8.x4.trans.shared.b16 {%0,%1,%2,%3}, [%4];"
        : "=r"(r[0]), "=r"(r[1]), "=r"(r[2]), "=r"(r[3]) : "r"(addr));
}
__device__ __forceinline__ void mma_bf16(float* c, const uint32_t* a,
                                         uint32_t b0, uint32_t b1)
{
    asm volatile(
        "mma.sync.aligned.m16n8k16.row.col.f32.bf16.bf16.f32 "
        "{%0,%1,%2,%3}, {%4,%5,%6,%7}, {%8,%9}, {%0,%1,%2,%3};\n"
        : "+f"(c[0]), "+f"(c[1]), "+f"(c[2]), "+f"(c[3])
        : "r"(a[0]), "r"(a[1]), "r"(a[2]), "r"(a[3]), "r"(b0), "r"(b1));
}
__device__ __forceinline__ void packsplit(float x, float y, uint32_t& hi, uint32_t& lo)
{
    bf16 hx = __float2bfloat16(x), hy = __float2bfloat16(y);
    hi = pack_bf16(hx, hy);
    lo = pack_bf16(__float2bfloat16(x - __bfloat162float(hx)),
                   __float2bfloat16(y - __bfloat162float(hy)));
}
__device__ __forceinline__ void cpa16(uint32_t dst, const void* src)
{
    asm volatile("cp.async.cg.shared.global [%0], [%1], 16;\n" :: "r"(dst), "l"(src));
}
__device__ __forceinline__ void cpa_commit()
{
    asm volatile("cp.async.commit_group;\n");
}
template<int N> __device__ __forceinline__ void cpa_wait()
{
    asm volatile("cp.async.wait_group %0;\n" :: "n"(N));
}
// GEMM smem swizzle: 64B rows (32 bf16), 4x16B chunks
__device__ __forceinline__ int swoff(int row, int chunk)
{
    return row * 64 + ((chunk ^ ((row >> 1) & 3)) * 16);
}
// attention plane swizzle: 128B rows (64 bf16), 8x16B chunks
__device__ __forceinline__ uint32_t swz128(int row, int c16)
{
    return (uint32_t)(row * 128 + ((c16 ^ (row & 7)) * 16));
}

// ------------------------- split-bf16 tensor-core GEMM (NT) ----------------
// C = A * B^T; A,B given as hi/lo bf16 planes (row-major, K contiguous).
// BM=128, BN=64, BK=32, 256 thr, 3-stage cp.async pipeline.
// ALO: include the A-lo correction term (Al*Bh). When false the GEMM runs
// 2 terms (Ah*Bh + Ah*Bl) and skips loading the Al plane entirely.
// OUTM: 0 = fp32 C, 1 = split hi/lo planes, 2 = hi plane only.
// QSCALEZ: blocks with blockIdx.z < QSCALEZ scale output by 1/temper.
#define GEMM_SMEM 73728

template<int QSCALEZ, bool RELU, bool HASBIAS, int OUTM, bool ALO>
__global__ __launch_bounds__(256, 2)
void mma_gemm_bf(const bf16* __restrict__ Ah, const bf16* __restrict__ Al,
                 const bf16* __restrict__ Bh, const bf16* __restrict__ Bl,
                 float* __restrict__ C, const float* __restrict__ bias,
                 bf16* __restrict__ Chi, bf16* __restrict__ Clo,
                 int M, int N, int K, long strideB, long strideC)
{
    extern __shared__ uint8_t sm[];
    Bh += (long)blockIdx.z * strideB;
    Bl += (long)blockIdx.z * strideB;
    if (OUTM == 0)      C   += (long)blockIdx.z * strideC;
    else {
        Chi += (long)blockIdx.z * strideC;
        if (OUTM == 1)  Clo += (long)blockIdx.z * strideC;
    }
    const int bm = blockIdx.y * 128, bn = blockIdx.x * 64;
    const int tid = threadIdx.x, lane = tid & 31, warp = tid >> 5;
    const int wm = (warp & 1) * 64, wn = (warp >> 1) * 16;
    const uint32_t sbase = (uint32_t)__cvta_generic_to_shared(sm);

    const int arow = tid >> 1, acb = (tid & 1) * 2;
    const int brow = tid >> 2, bcb = tid & 3;
    const long aoff = (long)(bm + arow) * K;
    const long boff = (long)(bn + brow) * K;
    const uint32_t ad0 = swoff(arow, acb), ad1 = swoff(arow, acb + 1);
    const uint32_t bd0 = swoff(brow, bcb);

    auto issue = [&](int slot, int k0) {
        const uint32_t s = sbase + slot * 24576;
        cpa16(s + ad0,         Ah + aoff + k0 + acb*8);
        cpa16(s + ad1,         Ah + aoff + k0 + acb*8 + 8);
        if (ALO) {
            cpa16(s + 8192 + ad0,  Al + aoff + k0 + acb*8);
            cpa16(s + 8192 + ad1,  Al + aoff + k0 + acb*8 + 8);
        }
        cpa16(s + 16384 + bd0, Bh + boff + k0 + bcb*8);
        cpa16(s + 20480 + bd0, Bl + boff + k0 + bcb*8);
    };

    float acc[4][2][4];
    #pragma unroll
    for (int mt = 0; mt < 4; ++mt)
        #pragma unroll
        for (int n2 = 0; n2 < 2; ++n2)
            #pragma unroll
            for (int j = 0; j < 4; ++j) acc[mt][n2][j] = 0.f;

    issue(0, 0);  cpa_commit();
    issue(1, 32); cpa_commit();

    const int nt = K / 32;
    #pragma unroll 1
    for (int t = 0; t < nt; ++t) {
        cpa_wait<1>();
        __syncthreads();
        const uint32_t aH = sbase + (t % 3) * 24576;
        const uint32_t aL = aH + 8192;
        const uint32_t bH = aH + 16384;
        const uint32_t bL = aH + 20480;
        #pragma unroll
        for (int kk = 0; kk < 2; ++kk) {
            const int kc = kk * 2 + (lane >> 4);
            const int br = wn + (lane & 15);
            uint32_t bhf[4], blf[4];
            ldsm4(bhf, bH + swoff(br, kc));
            ldsm4(blf, bL + swoff(br, kc));
            #pragma unroll
            for (int mt = 0; mt < 4; ++mt) {
                const int ar = wm + mt * 16 + (lane & 15);
                uint32_t ahf[4];
                ldsm4(ahf, aH + swoff(ar, kc));
                #pragma unroll
                for (int n2 = 0; n2 < 2; ++n2) {
                    mma_bf16(acc[mt][n2], ahf, bhf[n2], bhf[n2 + 2]);
                    mma_bf16(acc[mt][n2], ahf, blf[n2], blf[n2 + 2]);
                }
                if (ALO) {
                    uint32_t alf[4];
                    ldsm4(alf, aL + swoff(ar, kc));
                    #pragma unroll
                    for (int n2 = 0; n2 < 2; ++n2)
                        mma_bf16(acc[mt][n2], alf, bhf[n2], bhf[n2 + 2]);
                }
            }
        }
        if (t + 2 < nt) issue((t + 2) % 3, (t + 2) * 32);
        cpa_commit();
    }

    const bool qscale = (QSCALEZ > 0) && ((int)blockIdx.z < QSCALEZ);
    #pragma unroll
    for (int mt = 0; mt < 4; ++mt) {
        const int r0 = bm + wm + mt * 16 + (lane >> 2);
        #pragma unroll
        for (int n2 = 0; n2 < 2; ++n2) {
            const int col = bn + wn + n2 * 8 + (lane & 3) * 2;
            float2 v0 = { acc[mt][n2][0], acc[mt][n2][1] };
            float2 v1 = { acc[mt][n2][2], acc[mt][n2][3] };
            if (HASBIAS) {
                float b0 = bias[col], b1 = bias[col + 1];
                v0.x += b0; v0.y += b1; v1.x += b0; v1.y += b1;
            }
            if (RELU) {
                v0.x = fmaxf(v0.x, 0.f); v0.y = fmaxf(v0.y, 0.f);
                v1.x = fmaxf(v1.x, 0.f); v1.y = fmaxf(v1.y, 0.f);
            }
            if (QSCALEZ > 0 && qscale) {
                v0.x *= INV_TEMPER; v0.y *= INV_TEMPER;
                v1.x *= INV_TEMPER; v1.y *= INV_TEMPER;
            }
            if (OUTM == 1) {
                bf16 h0, l0, h1, l1, h2, l2, h3, l3;
                split1(v0.x, h0, l0); split1(v0.y, h1, l1);
                split1(v1.x, h2, l2); split1(v1.y, h3, l3);
                *(uint32_t*)(Chi + (long)r0 * N + col)       = pack_bf16(h0, h1);
                *(uint32_t*)(Chi + (long)(r0 + 8) * N + col) = pack_bf16(h2, h3);
                *(uint32_t*)(Clo + (long)r0 * N + col)       = pack_bf16(l0, l1);
                *(uint32_t*)(Clo + (long)(r0 + 8) * N + col) = pack_bf16(l2, l3);
            } else if (OUTM == 2) {
                *(uint32_t*)(Chi + (long)r0 * N + col) =
                    pack_bf16(__float2bfloat16(v0.x), __float2bfloat16(v0.y));
                *(uint32_t*)(Chi + (long)(r0 + 8) * N + col) =
                    pack_bf16(__float2bfloat16(v1.x), __float2bfloat16(v1.y));
            } else {
                *(float2*)(C + (long)r0 * N + col) = v0;
                *(float2*)(C + (long)(r0 + 8) * N + col) = v1;
            }
        }
    }
}

// ------------------------- FA2 tensor-core attention ----------------------
// R14 winner: 64-row q tile, 128 thr, occ 2. QK = 3 terms, PV = 2 terms.
#define FA_SMEM 81920
#define FA_STAGE 32768
#define ST_KH 0
#define ST_KL 8192
#define ST_VH 16384
#define ST_VL 24576
#define FA_QH 65536
#define FA_QL 73728

__global__ __launch_bounds__(128, 2)
void fa2_kernel(const bf16* __restrict__ QKVh,
                const bf16* __restrict__ QKVl,
                float* __restrict__ O)
{
    extern __shared__ uint8_t sm[];
    const uint32_t sbase = (uint32_t)__cvta_generic_to_shared(sm);

    const int h = blockIdx.z, b = blockIdx.y;
    const int q0 = blockIdx.x * 64;
    const int tid = threadIdx.x, lane = tid & 31, warp = tid >> 5;

    const long planeQ = ((long)h * NTOK + (long)b * SEQ) * DHEAD;
    const long planeK = ((long)(NHEAD + h) * NTOK + (long)b * SEQ) * DHEAD;
    const long planeV = ((long)(2*NHEAD + h) * NTOK + (long)b * SEQ) * DHEAD;

    int crow[4], cc16[4];
    #pragma unroll
    for (int p = 0; p < 4; ++p) {
        int ci = tid + p * 128;
        crow[p] = ci >> 3; cc16[p] = ci & 7;
    }

    #pragma unroll
    for (int p = 0; p < 4; ++p) {
        const uint32_t so = swz128(crow[p], cc16[p]);
        const long ro = (long)(q0 + crow[p]) * 64 + cc16[p] * 8;
        cpa16(sbase + FA_QH + so, QKVh + planeQ + ro);
        cpa16(sbase + FA_QL + so, QKVl + planeQ + ro);
    }
    cpa_commit();
    #pragma unroll
    for (int p = 0; p < 4; ++p) {
        const long ro = (long)crow[p] * 64 + cc16[p] * 8;
        const uint32_t so = swz128(crow[p], cc16[p]);
        cpa16(sbase + ST_KH + so, QKVh + planeK + ro);
        cpa16(sbase + ST_KL + so, QKVl + planeK + ro);
        cpa16(sbase + ST_VH + so, QKVh + planeV + ro);
        cpa16(sbase + ST_VL + so, QKVl + planeV + ro);
    }
    cpa_commit();

    cpa_wait<1>();
    __syncthreads();

    uint32_t qh[4][4], ql[4][4];
    {
        const int qrow = warp * 16 + (lane & 15);
        #pragma unroll
        for (int ks = 0; ks < 4; ++ks) {
            ldsm4(qh[ks], sbase + FA_QH + swz128(qrow, 2*ks + (lane >> 4)));
            ldsm4(ql[ks], sbase + FA_QL + swz128(qrow, 2*ks + (lane >> 4)));
        }
    }

    float o[8][4];
    #pragma unroll
    for (int vt = 0; vt < 8; ++vt)
        #pragma unroll
        for (int j = 0; j < 4; ++j) o[vt][j] = 0.f;
    float run_m0 = -INFINITY, run_m1 = -INFINITY;
    float run_l0 = 0.f, run_l1 = 0.f;

    #pragma unroll 1
    for (int c = 0; c < 16; ++c) {
        const uint32_t stg = sbase + (c & 1) * FA_STAGE;
        if (c < 15) {
            const uint32_t nst = sbase + ((c + 1) & 1) * FA_STAGE;
            const long m0 = (long)(c + 1) * 64;
            #pragma unroll
            for (int p = 0; p < 4; ++p) {
                const long ro = (m0 + crow[p]) * 64 + cc16[p] * 8;
                const uint32_t so = swz128(crow[p], cc16[p]);
                cpa16(nst + ST_KH + so, QKVh + planeK + ro);
                cpa16(nst + ST_KL + so, QKVl + planeK + ro);
                cpa16(nst + ST_VH + so, QKVh + planeV + ro);
                cpa16(nst + ST_VL + so, QKVl + planeV + ro);
            }
            cpa_commit();
            cpa_wait<1>();
        } else {
            cpa_wait<0>();
        }
        __syncthreads();

        // ---- S = Q K^T (split bf16, 3 terms), 8 n8-tiles (64 K rows)
        float s[8][4];
        #pragma unroll
        for (int t = 0; t < 8; ++t)
            #pragma unroll
            for (int j = 0; j < 4; ++j) s[t][j] = 0.f;
        #pragma unroll
        for (int g = 0; g < 4; ++g) {
            const int krow = g * 16 + (lane & 15);
            #pragma unroll
            for (int ks = 0; ks < 4; ++ks) {
                const uint32_t so = swz128(krow, 2*ks + (lane >> 4));
                uint32_t khf[4], klf[4];
                ldsm4(khf, stg + ST_KH + so);
                ldsm4(klf, stg + ST_KL + so);
                #pragma unroll
                for (int n2 = 0; n2 < 2; ++n2) {
                    float* st = s[g*2 + n2];
                    mma_bf16(st, qh[ks], khf[n2], khf[n2 + 2]);
                    mma_bf16(st, qh[ks], klf[n2], klf[n2 + 2]);
                    mma_bf16(st, ql[ks], khf[n2], khf[n2 + 2]);
                }
            }
        }

        // ---- online softmax (rows r = lane>>2, r+8); scores pre-scaled
        float mx0 = -INFINITY, mx1 = -INFINITY;
        #pragma unroll
        for (int t = 0; t < 8; ++t) {
            mx0 = fmaxf(mx0, fmaxf(s[t][0], s[t][1]));
            mx1 = fmaxf(mx1, fmaxf(s[t][2], s[t][3]));
        }
        mx0 = fmaxf(mx0, __shfl_xor_sync(0xffffffffu, mx0, 1));
        mx0 = fmaxf(mx0, __shfl_xor_sync(0xffffffffu, mx0, 2));
        mx1 = fmaxf(mx1, __shfl_xor_sync(0xffffffffu, mx1, 1));
        mx1 = fmaxf(mx1, __shfl_xor_sync(0xffffffffu, mx1, 2));

        const float nm0 = fmaxf(run_m0, mx0);
        const float nm1 = fmaxf(run_m1, mx1);
        const float sc0 = __expf(run_m0 - nm0);
        const float sc1 = __expf(run_m1 - nm1);
        run_m0 = nm0; run_m1 = nm1;

        float ps0 = 0.f, ps1 = 0.f;
        #pragma unroll
        for (int t = 0; t < 8; ++t) {
            float p0 = __expf(s[t][0] - nm0); s[t][0] = p0;
            float p1 = __expf(s[t][1] - nm0); s[t][1] = p1;
            float p2 = __expf(s[t][2] - nm1); s[t][2] = p2;
            float p3 = __expf(s[t][3] - nm1); s[t][3] = p3;
            ps0 += p0 + p1; ps1 += p2 + p3;
        }
        run_l0 = run_l0 * sc0 + ps0;
        run_l1 = run_l1 * sc1 + ps1;
        #pragma unroll
        for (int vt = 0; vt < 8; ++vt) {
            o[vt][0] *= sc0; o[vt][1] *= sc0;
            o[vt][2] *= sc1; o[vt][3] *= sc1;
        }

        // ---- O += P V : 2 terms (Ph*Vh + Ph*Vl)
        #pragma unroll
        for (int ks = 0; ks < 4; ++ks) {
            uint32_t ah[4];
            ah[0] = pack_bf16(__float2bfloat16(s[2*ks][0]),   __float2bfloat16(s[2*ks][1]));
            ah[1] = pack_bf16(__float2bfloat16(s[2*ks][2]),   __float2bfloat16(s[2*ks][3]));
            ah[2] = pack_bf16(__float2bfloat16(s[2*ks+1][0]), __float2bfloat16(s[2*ks+1][1]));
            ah[3] = pack_bf16(__float2bfloat16(s[2*ks+1][2]), __float2bfloat16(s[2*ks+1][3]));
            const int vrow = ks * 16 + (lane & 15);
            #pragma unroll
            for (int vg = 0; vg < 4; ++vg) {
                const uint32_t so = swz128(vrow, vg*2 + (lane >> 4));
                uint32_t vhf[4], vlf[4];
                ldsm4t(vhf, stg + ST_VH + so);
                ldsm4t(vlf, stg + ST_VL + so);
                #pragma unroll
                for (int n2 = 0; n2 < 2; ++n2) {
                    float* ot = o[vg*2 + n2];
                    mma_bf16(ot, ah, vhf[2*n2], vhf[2*n2 + 1]);
                    mma_bf16(ot, ah, vlf[2*n2], vlf[2*n2 + 1]);
                }
            }
        }
        __syncthreads();
    }

    run_l0 += __shfl_xor_sync(0xffffffffu, run_l0, 1);
    run_l0 += __shfl_xor_sync(0xffffffffu, run_l0, 2);
    run_l1 += __shfl_xor_sync(0xffffffffu, run_l1, 1);
    run_l1 += __shfl_xor_sync(0xffffffffu, run_l1, 2);
    const float inv0 = 1.f / run_l0, inv1 = 1.f / run_l1;

    const int r  = q0 + warp * 16 + (lane >> 2);
    const int cb = h * 64 + (lane & 3) * 2;
    #pragma unroll
    for (int vt = 0; vt < 8; ++vt) {
        float2 v0 = { o[vt][0] * inv0, o[vt][1] * inv0 };
        float2 v1 = { o[vt][2] * inv1, o[vt][3] * inv1 };
        *(float2*)(O + ((long)b*SEQ + r)     * DMODEL + cb + vt*8) = v0;
        *(float2*)(O + ((long)b*SEQ + r + 8) * DMODEL + cb + vt*8) = v1;
    }
}

// ------------------------- residual + LayerNorm (+ split planes) ----------
// Single fused reduction tree: (sum, sumsq) in one pass.
__global__ void ln_kernel(const float* __restrict__ X, const float* __restrict__ R,
                          const float* __restrict__ gamma, const float* __restrict__ beta,
                          float* __restrict__ Y,
                          bf16* __restrict__ Yh, bf16* __restrict__ Yl)
{
    const long row = blockIdx.x;
    const int tid = threadIdx.x;           // 128 threads, 4 elems each
    __shared__ float2 red[128];
    const int i = tid * 4;
    float4 a = *(const float4*)(X + row*DMODEL + i);
    float4 b = *(const float4*)(R + row*DMODEL + i);
    float z0 = a.x + b.x, z1 = a.y + b.y, z2 = a.z + b.z, z3 = a.w + b.w;

    float s  = z0 + z1 + z2 + z3;
    float sq = z0*z0 + z1*z1 + z2*z2 + z3*z3;
    red[tid] = make_float2(s, sq); __syncthreads();
    for (int st = 64; st > 0; st >>= 1) {
        if (tid < st) {
            red[tid].x += red[tid+st].x;
            red[tid].y += red[tid+st].y;
        }
        __syncthreads();
    }
    const float mu = red[0].x * (1.f / DMODEL);
    const float ss = red[0].y - DMODEL * mu * mu;
    const float sigma = sqrtf(fmaxf(ss, 0.f) * (1.f / (DMODEL - 1)));
    const float sc = 1.f / (sigma + EPS);

    float d0 = z0-mu, d1 = z1-mu, d2 = z2-mu, d3 = z3-mu;
    float4 g4 = *(const float4*)(gamma + i);
    float4 be = *(const float4*)(beta + i);
    float4 y;
    y.x = d0 * sc * g4.x + be.x;
    y.y = d1 * sc * g4.y + be.y;
    y.z = d2 * sc * g4.z + be.z;
    y.w = d3 * sc * g4.w + be.w;
    *(float4*)(Y + row*DMODEL + i) = y;

    bf16 h0,l0,h1,l1,h2,l2,h3,l3;
    split1(y.x,h0,l0); split1(y.y,h1,l1); split1(y.z,h2,l2); split1(y.w,h3,l3);
    *(uint2*)(Yh + row*DMODEL + i) = make_uint2(pack_bf16(h0,h1), pack_bf16(h2,h3));
    *(uint2*)(Yl + row*DMODEL + i) = make_uint2(pack_bf16(l0,l1), pack_bf16(l2,l3));
}

// ------------------------- launch ------------------------------------------
extern "C" void kernel_launch(void* const* d_in, const int* in_sizes, int n_in,
                              void* d_out, int out_size)
{
    (void)in_sizes; (void)n_in; (void)out_size;
    const float* x    = (const float*)d_in[0];
    const float* pos  = (const float*)d_in[1];
    const float* wq   = (const float*)d_in[2];
    const float* wk   = (const float*)d_in[3];
    const float* wv   = (const float*)d_in[4];
    const float* ln1a = (const float*)d_in[5];
    const float* ln1b = (const float*)d_in[6];
    const float* w1   = (const float*)d_in[7];
    const float* b1   = (const float*)d_in[8];
    const float* w2   = (const float*)d_in[9];
    const float* b2   = (const float*)d_in[10];
    const float* ln2a = (const float*)d_in[11];
    const float* ln2b = (const float*)d_in[12];
    float* out = (float*)d_out;

    float *gx, *ga, *go;
    bf16 *xh, *xl, *hh, *wqkvh, *wqkvl, *w1h, *w1l, *w2h, *w2l, *qkvh, *qkvl;
    cudaGetSymbolAddress((void**)&gx, g_x);
    cudaGetSymbolAddress((void**)&ga, g_att);
    cudaGetSymbolAddress((void**)&go, g_o);
    cudaGetSymbolAddress((void**)&xh, g_xh);
    cudaGetSymbolAddress((void**)&xl, g_xl);
    cudaGetSymbolAddress((void**)&hh, g_hh);
    cudaGetSymbolAddress((void**)&wqkvh, g_wqkvh);
    cudaGetSymbolAddress((void**)&wqkvl, g_wqkvl);
    cudaGetSymbolAddress((void**)&w1h, g_w1h);
    cudaGetSymbolAddress((void**)&w1l, g_w1l);
    cudaGetSymbolAddress((void**)&w2h, g_w2h);
    cudaGetSymbolAddress((void**)&w2l, g_w2l);
    cudaGetSymbolAddress((void**)&qkvh, g_qkv_h);
    cudaGetSymbolAddress((void**)&qkvl, g_qkv_l);

    static bool attr_set = false;
    if (!attr_set) {
        cudaFuncSetAttribute(fa2_kernel,
                             cudaFuncAttributeMaxDynamicSharedMemorySize, FA_SMEM);
        cudaFuncSetAttribute(mma_gemm_bf<8,false,false,1,true>,
                             cudaFuncAttributeMaxDynamicSharedMemorySize, GEMM_SMEM);
        cudaFuncSetAttribute(mma_gemm_bf<0,true,true,2,false>,
                             cudaFuncAttributeMaxDynamicSharedMemorySize, GEMM_SMEM);
        cudaFuncSetAttribute(mma_gemm_bf<0,false,true,0,false>,
                             cudaFuncAttributeMaxDynamicSharedMemorySize, GEMM_SMEM);
        attr_set = true;
    }

    // prep: positional add (+ split), weight transpose/split
    add_pos_kernel<<<NTOK*DMODEL/512, 512>>>(x, pos, gx, xh, xl);
    transpose3_kernel<<<dim3(DHEAD/32, DMODEL/32, 3*NLAYERS*NHEAD), dim3(32,8)>>>(
        wq, wk, wv, wqkvh, wqkvl);
    split_kernel<<<NLAYERS*DINNER*DMODEL/1024, 256>>>(w1, w1h, w1l, NLAYERS*DINNER*DMODEL);
    split_kernel<<<NLAYERS*DMODEL*DINNER/1024, 256>>>(w2, w2h, w2l, NLAYERS*DMODEL*DINNER);

    const long wqkv_mat   = (long)DHEAD * DMODEL;
    const long wqkv_layer = 3L * NHEAD * wqkv_mat;
    const long qkv_mat    = (long)NTOK * DHEAD;

    for (int i = 0; i < NLAYERS; ++i) {
        // fused QKV: 24 mats [4096,512]x[64,512]^T -> split planes, 3 terms
        // (z<8 = Q heads get pre-scaled by 1/temper in the epilogue)
        mma_gemm_bf<8,false,false,1,true><<<dim3(1, NTOK/128, 3*NHEAD), 256, GEMM_SMEM>>>(
            xh, xl, wqkvh + i*wqkv_layer, wqkvl + i*wqkv_layer,
            nullptr, nullptr, qkvh, qkvl,
            NTOK, DHEAD, DMODEL, wqkv_mat, qkv_mat);

        fa2_kernel<<<dim3(SEQ/64, BATCH, NHEAD), 128, FA_SMEM>>>(qkvh, qkvl, ga);

        ln_kernel<<<NTOK, 128>>>(ga, gx, ln1a + i*DMODEL, ln1b + i*DMODEL, gx, xh, xl);

        // FFN1: h = relu(x @ w1^T + b1) -> hi plane only; 2 terms
        mma_gemm_bf<0,true,true,2,false><<<dim3(DINNER/64, NTOK/128, 1), 256, GEMM_SMEM>>>(
            xh, xl, w1h + (long)i*DINNER*DMODEL, w1l + (long)i*DINNER*DMODEL,
            nullptr, b1 + i*DINNER, hh, nullptr,
            NTOK, DINNER, DMODEL, 0, 0);
        // FFN2: o = h @ w2^T + b2 -> fp32; 2 terms (h-lo dropped: error
        // smoothed through the 1024-wide random-sign sum, ~4.5e-4 contribution)
        mma_gemm_bf<0,false,true,0,false><<<dim3(DMODEL/64, NTOK/128, 1), 256, GEMM_SMEM>>>(
            hh, nullptr, w2h + (long)i*DMODEL*DINNER, w2l + (long)i*DMODEL*DINNER,
            go, b2 + i*DMODEL, nullptr, nullptr,
            NTOK, DMODEL, DINNER, 0, 0);

        ln_kernel<<<NTOK, 128>>>(go, gx, ln2a + i*DMODEL, ln2b + i*DMODEL, gx, xh, xl);
    }

    cudaMemcpyAsync(out, gx, (size_t)NTOK*DMODEL*sizeof(float),
                    cudaMemcpyDeviceToDevice);
}